// round 7
// baseline (speedup 1.0000x reference)
#include <cuda_runtime.h>
#include <math.h>
#include <stdint.h>

#define Bb 8
#define Tt 8192
#define Ss 8192
#define Ff 64
#define Dd 64
#define EPSf 1e-9f
#define KVPAD 72
#define ASPLITS 16
#define AROWS (Ss/ASPLITS)   /* 512 rows per block in kv kernel */

// kv scratch [b][256][72]; cols 65..71 stay zero
__device__ __align__(16) float g_kv[Bb * 256 * KVPAD];

// ---------------------------------------------------------------------------
// helpers
// ---------------------------------------------------------------------------
__device__ __forceinline__ float ftf32(float x) {
    unsigned u;
    asm("cvt.rna.tf32.f32 %0, %1;" : "=r"(u) : "f"(x));
    return __uint_as_float(u);
}

__device__ __forceinline__ void mma8(float4& d,
                                     float a0, float a1, float a2, float a3,
                                     float b0, float b1) {
    asm("mma.sync.aligned.m16n8k8.row.col.f32.tf32.tf32.f32 "
        "{%0,%1,%2,%3},{%4,%5,%6,%7},{%8,%9},{%0,%1,%2,%3};"
        : "+f"(d.x), "+f"(d.y), "+f"(d.z), "+f"(d.w)
        : "r"(__float_as_uint(a0)), "r"(__float_as_uint(a1)),
          "r"(__float_as_uint(a2)), "r"(__float_as_uint(a3)),
          "r"(__float_as_uint(b0)), "r"(__float_as_uint(b1)));
}

__global__ void zero_kv_kernel() {
    int i = blockIdx.x * blockDim.x + threadIdx.x;
    if (i < Bb * 256 * KVPAD) g_kv[i] = 0.0f;
}

// ---------------------------------------------------------------------------
// smem layouts (float offsets)
// ---------------------------------------------------------------------------
// kernel A
#define A_KS   0        /* [64][68]  */
#define A_VS   4352     /* [64][72]  */
#define A_PHT  8960     /* [256][68] */
#define A_OHI  26368    /* [128][68] */
#define A_OLO  35072    /* [128][68] */
#define A_SSH  43776    /* [64]      */
#define A_PRT  43840    /* [512]     */
#define A_TOT  44352
// kernel B
#define B_PHIQ 0        /* [128][260], aliases Qs/Ohi/Olo during phase 1 */
#define B_QS   0        /* [128][68]  */
#define B_OHI  8704     /* [128][68]  */
#define B_OLO  17408    /* [128][68]  */
#define B_KVS  33280    /* [256][72]  */
#define B_SSH  51712    /* [128]; reused as 1/norm after epilogue  */
#define B_PRT  51840    /* [512]      */
#define B_TOT  52352

extern __shared__ float sm[];

// ---------------------------------------------------------------------------
// Kernel A: fused  K -> phi_k -> kv partial (split-K over S, atomics)
// block: 512 thr / 16 warps, 1 block/SM.  Per 64-row chunk:
//   XW[64x128] = K_chunk . Omega^T   (split tf32, warp owns 8 features)
//   PhT[256][64] = exp(+-XW - ss) + eps  (tf32, transposed)
//   acc[16 rows x 64] += PhT . V_chunk   (warp owns 16 kv rows)
// ---------------------------------------------------------------------------
__global__ __launch_bounds__(512, 1)
void kv_kernel(const float* __restrict__ key,
               const float* __restrict__ value,
               const float* __restrict__ omega) {
    const int b   = blockIdx.y;
    const int tid = threadIdx.x;
    const int w   = tid >> 5;          // 0..15
    const int ln  = tid & 31;
    const int gid = ln >> 2;
    const int tq  = ln & 3;

    float* Ks  = sm + A_KS;
    float* Vs  = sm + A_VS;
    float* PhT = sm + A_PHT;
    float* Ohi = sm + A_OHI;
    float* Olo = sm + A_OLO;
    float* ssh = sm + A_SSH;
    float* prt = sm + A_PRT;

    // omega -> hi/lo tf32 split in smem
    for (int i = tid; i < 128 * 64; i += 512) {
        int m = i >> 6, f = i & 63;
        float x  = omega[i];
        float hi = ftf32(x);
        Ohi[m * 68 + f] = hi;
        Olo[m * 68 + f] = ftf32(x - hi);
    }

    float4 acc[8];
    #pragma unroll
    for (int nt = 0; nt < 8; nt++) acc[nt] = make_float4(0.f, 0.f, 0.f, 0.f);
    float nrm0 = 0.f, nrm1 = 0.f;

    const int row0base = blockIdx.x * AROWS;

    for (int c = 0; c < AROWS / 64; c++) {
        __syncthreads();   // previous-iter PhT reads done before overwrite
        const int row0 = row0base + c * 64;

        // ---- load K chunk (+ssq partials) and V chunk (tf32-rounded) ----
        {
            int r = tid >> 3, j8 = tid & 7;      // 8 threads per row, 2 f4 each
            const float4* kg = (const float4*)(key + ((size_t)(b * Ss + row0 + r)) * Ff);
            float ps = 0.f;
            #pragma unroll
            for (int h = 0; h < 2; h++) {
                int j = j8 + h * 8;
                float4 x = kg[j];
                ps += x.x * x.x + x.y * x.y + x.z * x.z + x.w * x.w;
                ((float4*)(Ks + r * 68))[j] = x;
            }
            prt[tid] = ps;
            const float4* vg = (const float4*)(value + ((size_t)(b * Ss + row0 + r)) * Dd);
            #pragma unroll
            for (int h = 0; h < 2; h++) {
                int j = j8 + h * 8;
                float4 x = vg[j];
                float4 y;
                y.x = ftf32(x.x); y.y = ftf32(x.y); y.z = ftf32(x.z); y.w = ftf32(x.w);
                ((float4*)(Vs + r * 72))[j] = y;
            }
        }
        __syncthreads();
        if (tid < 64) {
            float s = 0.f;
            #pragma unroll
            for (int j = 0; j < 8; j++) s += prt[tid * 8 + j];
            ssh[tid] = 0.5f * s;
        }
        __syncthreads();

        // ---- XW = K . Omega^T  (warp w owns features [8w, 8w+8)) ----
        float4 xw[4];
        #pragma unroll
        for (int mt = 0; mt < 4; mt++) xw[mt] = make_float4(0.f, 0.f, 0.f, 0.f);

        const int mfeat = w * 8 + gid;
        for (int ks = 0; ks < 8; ks++) {
            int f0 = ks * 8 + tq;
            float bh0 = Ohi[mfeat * 68 + f0], bh1 = Ohi[mfeat * 68 + f0 + 4];
            float bl0 = Olo[mfeat * 68 + f0], bl1 = Olo[mfeat * 68 + f0 + 4];
            #pragma unroll
            for (int mt = 0; mt < 4; mt++) {
                int s = mt * 16 + gid;
                float a0 = Ks[s * 68 + f0],       a1 = Ks[(s + 8) * 68 + f0];
                float a2 = Ks[s * 68 + f0 + 4],   a3 = Ks[(s + 8) * 68 + f0 + 4];
                float h0 = ftf32(a0), h1 = ftf32(a1), h2 = ftf32(a2), h3 = ftf32(a3);
                float l0 = ftf32(a0 - h0), l1 = ftf32(a1 - h1);
                float l2 = ftf32(a2 - h2), l3 = ftf32(a3 - h3);
                mma8(xw[mt], h0, h1, h2, h3, bh0, bh1);
                mma8(xw[mt], l0, l1, l2, l3, bh0, bh1);
                mma8(xw[mt], h0, h1, h2, h3, bl0, bl1);
            }
        }

        // ---- phi epilogue: PhT[m][s] = tf32(exp(+-xw - ss) + eps) ----
        {
            int m0 = w * 8 + 2 * tq;
            #pragma unroll
            for (int mt = 0; mt < 4; mt++) {
                int s0 = mt * 16 + gid;
                float ssa = ssh[s0], ssb = ssh[s0 + 8];
                float4 v = xw[mt];
                PhT[m0 * 68 + s0]             = ftf32(__expf( v.x - ssa) + EPSf);
                PhT[(m0 + 1) * 68 + s0]       = ftf32(__expf( v.y - ssa) + EPSf);
                PhT[m0 * 68 + s0 + 8]         = ftf32(__expf( v.z - ssb) + EPSf);
                PhT[(m0 + 1) * 68 + s0 + 8]   = ftf32(__expf( v.w - ssb) + EPSf);
                PhT[(m0 + 128) * 68 + s0]     = ftf32(__expf(-v.x - ssa) + EPSf);
                PhT[(m0 + 129) * 68 + s0]     = ftf32(__expf(-v.y - ssa) + EPSf);
                PhT[(m0 + 128) * 68 + s0 + 8] = ftf32(__expf(-v.z - ssb) + EPSf);
                PhT[(m0 + 129) * 68 + s0 + 8] = ftf32(__expf(-v.w - ssb) + EPSf);
            }
        }
        __syncthreads();

        // ---- acc += PhT . V   (warp w owns kv rows [16w, 16w+16)) ----
        const int mr = 16 * w + gid;
        #pragma unroll 2
        for (int ks = 0; ks < 8; ks++) {
            int sc = ks * 8 + tq;
            float a0 = PhT[mr * 68 + sc];
            float a1 = PhT[(mr + 8) * 68 + sc];
            float a2 = PhT[mr * 68 + sc + 4];
            float a3 = PhT[(mr + 8) * 68 + sc + 4];
            // normalizer: each phi of this thread's rows appears exactly once
            nrm0 += a0 + a2;
            nrm1 += a1 + a3;
            #pragma unroll
            for (int nt = 0; nt < 8; nt++) {
                float b0 = Vs[sc * 72 + nt * 8 + gid];
                float b1 = Vs[(sc + 4) * 72 + nt * 8 + gid];
                mma8(acc[nt], a0, a1, a2, a3, b0, b1);
            }
        }
    }

    // ---- atomic reduce into g_kv ----
    float* gp = g_kv + (size_t)b * 256 * KVPAD;
    {
        int m0 = 16 * w + gid;
        #pragma unroll
        for (int nt = 0; nt < 8; nt++) {
            int d0 = nt * 8 + 2 * tq;
            atomicAdd(gp + m0 * KVPAD + d0,           acc[nt].x);
            atomicAdd(gp + m0 * KVPAD + d0 + 1,       acc[nt].y);
            atomicAdd(gp + (m0 + 8) * KVPAD + d0,     acc[nt].z);
            atomicAdd(gp + (m0 + 8) * KVPAD + d0 + 1, acc[nt].w);
        }
        float n0 = nrm0, n1 = nrm1;
        n0 += __shfl_xor_sync(0xffffffffu, n0, 1);
        n0 += __shfl_xor_sync(0xffffffffu, n0, 2);
        n1 += __shfl_xor_sync(0xffffffffu, n1, 1);
        n1 += __shfl_xor_sync(0xffffffffu, n1, 2);
        if (tq == 0) {
            atomicAdd(gp + m0 * KVPAD + 64,       n0);
            atomicAdd(gp + (m0 + 8) * KVPAD + 64, n1);
        }
    }
}

// ---------------------------------------------------------------------------
// Kernel B GEMM4 helper: warp processes n-tiles [NT0, NT0+NTN)
// ---------------------------------------------------------------------------
template<int NT0, int NTN>
__device__ __forceinline__ void gemm4_run(const float* PhiQ, const float* kvs,
                                          int tr, int tq, int gid,
                                          float4* oacc) {
    #pragma unroll 4
    for (int ks = 0; ks < 32; ks++) {
        int mc = ks * 8 + tq;
        float a0 = PhiQ[tr * 260 + mc];
        float a1 = PhiQ[(tr + 8) * 260 + mc];
        float a2 = PhiQ[tr * 260 + mc + 4];
        float a3 = PhiQ[(tr + 8) * 260 + mc + 4];
        #pragma unroll
        for (int i = 0; i < NTN; i++) {
            int nt = NT0 + i;
            float b0 = kvs[mc * KVPAD + nt * 8 + gid];
            float b1 = kvs[(mc + 4) * KVPAD + nt * 8 + gid];
            mma8(oacc[i], a0, a1, a2, a3, b0, b1);
        }
    }
}

// ---------------------------------------------------------------------------
// Kernel B: fused  Q -> phi_q -> out = (phi_q . kv) / normalizer
// block: 512 thr / 16 warps, 128 t-rows per block.
// GEMM1: warp owns 8 features.  GEMM4: warp pair splits 9 n-tiles 5/4.
// ---------------------------------------------------------------------------
__global__ __launch_bounds__(512, 1)
void out_kernel(const float* __restrict__ query,
                const float* __restrict__ omega,
                float* __restrict__ outp) {
    const int b   = blockIdx.y;
    const int t0  = blockIdx.x * 128;
    const int tid = threadIdx.x;
    const int w   = tid >> 5;          // 0..15
    const int ln  = tid & 31;
    const int gid = ln >> 2;
    const int tq  = ln & 3;

    float* PhiQ = sm + B_PHIQ;
    float* Qs   = sm + B_QS;
    float* Ohi  = sm + B_OHI;
    float* Olo  = sm + B_OLO;
    float* kvs  = sm + B_KVS;
    float* ssh  = sm + B_SSH;
    float* prt  = sm + B_PRT;

    // ---- phase-1 loads: Q tile, omega hi/lo, kv (tf32-rounded) ----
    {
        int r = tid >> 2, qd = tid & 3;    // 4 threads per row, 4 f4 each
        const float4* qg = (const float4*)(query + ((size_t)(b * Tt + t0 + r)) * Ff);
        float ps = 0.f;
        #pragma unroll
        for (int j = 0; j < 4; j++) {
            float4 x = qg[qd * 4 + j];
            ps += x.x * x.x + x.y * x.y + x.z * x.z + x.w * x.w;
            ((float4*)(Qs + r * 68))[qd * 4 + j] = x;
        }
        prt[tid] = ps;
    }
    for (int i = tid; i < 128 * 64; i += 512) {
        int m = i >> 6, f = i & 63;
        float x  = omega[i];
        float hi = ftf32(x);
        Ohi[m * 68 + f] = hi;
        Olo[m * 68 + f] = ftf32(x - hi);
    }
    {
        const float4* gk = (const float4*)(g_kv + (size_t)b * 256 * KVPAD);
        for (int i = tid; i < 256 * KVPAD / 4; i += 512) {
            float4 x = gk[i];
            float4 y;
            y.x = ftf32(x.x); y.y = ftf32(x.y); y.z = ftf32(x.z); y.w = ftf32(x.w);
            ((float4*)kvs)[i] = y;
        }
    }
    __syncthreads();
    if (tid < 128)
        ssh[tid] = 0.5f * (prt[4 * tid] + prt[4 * tid + 1] +
                           prt[4 * tid + 2] + prt[4 * tid + 3]);
    __syncthreads();

    // ---- XW = Q . Omega^T  (warp w owns features [8w, 8w+8)) ----
    float4 xw[8];
    #pragma unroll
    for (int mt = 0; mt < 8; mt++) xw[mt] = make_float4(0.f, 0.f, 0.f, 0.f);

    const int mfeat = w * 8 + gid;
    for (int ks = 0; ks < 8; ks++) {
        int f0 = ks * 8 + tq;
        float bh0 = Ohi[mfeat * 68 + f0], bh1 = Ohi[mfeat * 68 + f0 + 4];
        float bl0 = Olo[mfeat * 68 + f0], bl1 = Olo[mfeat * 68 + f0 + 4];
        #pragma unroll
        for (int mt = 0; mt < 8; mt++) {
            int t = mt * 16 + gid;
            float a0 = Qs[t * 68 + f0],       a1 = Qs[(t + 8) * 68 + f0];
            float a2 = Qs[t * 68 + f0 + 4],   a3 = Qs[(t + 8) * 68 + f0 + 4];
            float h0 = ftf32(a0), h1 = ftf32(a1), h2 = ftf32(a2), h3 = ftf32(a3);
            float l0 = ftf32(a0 - h0), l1 = ftf32(a1 - h1);
            float l2 = ftf32(a2 - h2), l3 = ftf32(a3 - h3);
            mma8(xw[mt], h0, h1, h2, h3, bh0, bh1);
            mma8(xw[mt], l0, l1, l2, l3, bh0, bh1);
            mma8(xw[mt], h0, h1, h2, h3, bl0, bl1);
        }
    }
    __syncthreads();   // all Qs/omega reads done; PhiQ may overwrite them now

    // ---- phi epilogue: PhiQ[t][m] = tf32(exp(+-xw - ss) + eps) ----
    {
        int m0 = w * 8 + 2 * tq;
        #pragma unroll
        for (int mt = 0; mt < 8; mt++) {
            int t = mt * 16 + gid;
            float ssa = ssh[t], ssb = ssh[t + 8];
            float4 v = xw[mt];
            PhiQ[t * 260 + m0]             = ftf32(__expf( v.x - ssa) + EPSf);
            PhiQ[t * 260 + m0 + 1]         = ftf32(__expf( v.y - ssa) + EPSf);
            PhiQ[(t + 8) * 260 + m0]       = ftf32(__expf( v.z - ssb) + EPSf);
            PhiQ[(t + 8) * 260 + m0 + 1]   = ftf32(__expf( v.w - ssb) + EPSf);
            PhiQ[t * 260 + m0 + 128]       = ftf32(__expf(-v.x - ssa) + EPSf);
            PhiQ[t * 260 + m0 + 129]       = ftf32(__expf(-v.y - ssa) + EPSf);
            PhiQ[(t + 8) * 260 + m0 + 128] = ftf32(__expf(-v.z - ssb) + EPSf);
            PhiQ[(t + 8) * 260 + m0 + 129] = ftf32(__expf(-v.w - ssb) + EPSf);
        }
    }
    __syncthreads();

    // ---- out = PhiQ . kv  (warp pair: wr owns t-rows [16wr,16wr+16),
    //      half 0 -> n-tiles 0..4, half 1 -> n-tiles 5..8 (incl. normalizer)) ----
    const int half = w >> 3;
    const int wr   = w & 7;
    const int tr   = 16 * wr + gid;

    float4 oacc[5];
    #pragma unroll
    for (int i = 0; i < 5; i++) oacc[i] = make_float4(0.f, 0.f, 0.f, 0.f);

    if (half == 0) gemm4_run<0, 5>(PhiQ, kvs, tr, tq, gid, oacc);
    else           gemm4_run<5, 4>(PhiQ, kvs, tr, tq, gid, oacc);

    // normalizer lives in n-tile 8 (half==1, i==3), col 64 -> lanes tq==0
    if (half == 1) {
        float n0 = __shfl_sync(0xffffffffu, oacc[3].x, ln & ~3);
        float n1 = __shfl_sync(0xffffffffu, oacc[3].z, ln & ~3);
        if (tq == 0) {
            ssh[tr]     = 1.0f / n0;   // ssh reused: 1/normalizer per t-row
            ssh[tr + 8] = 1.0f / n1;
        }
    }
    __syncthreads();

    float inv0 = ssh[tr];
    float inv1 = ssh[tr + 8];

    size_t orow = ((size_t)b * Tt + t0 + tr) * 64;
    if (half == 0) {
        #pragma unroll
        for (int i = 0; i < 5; i++) {
            int col = i * 8 + 2 * tq;
            *(float2*)(outp + orow + col) =
                make_float2(oacc[i].x * inv0, oacc[i].y * inv0);
            *(float2*)(outp + orow + 8 * 64 + col) =
                make_float2(oacc[i].z * inv1, oacc[i].w * inv1);
        }
    } else {
        #pragma unroll
        for (int i = 0; i < 3; i++) {
            int col = (5 + i) * 8 + 2 * tq;
            *(float2*)(outp + orow + col) =
                make_float2(oacc[i].x * inv0, oacc[i].y * inv0);
            *(float2*)(outp + orow + 8 * 64 + col) =
                make_float2(oacc[i].z * inv1, oacc[i].w * inv1);
        }
    }
}

// ---------------------------------------------------------------------------
// launch
// ---------------------------------------------------------------------------
extern "C" void kernel_launch(void* const* d_in, const int* in_sizes, int n_in,
                              void* d_out, int out_size) {
    const float* query = (const float*)d_in[0];
    const float* value = (const float*)d_in[1];
    const float* key   = (const float*)d_in[2];
    const float* omega = (const float*)d_in[3];
    float* out = (float*)d_out;

    cudaFuncSetAttribute(kv_kernel,  cudaFuncAttributeMaxDynamicSharedMemorySize,
                         A_TOT * (int)sizeof(float));
    cudaFuncSetAttribute(out_kernel, cudaFuncAttributeMaxDynamicSharedMemorySize,
                         B_TOT * (int)sizeof(float));

    zero_kv_kernel<<<(Bb * 256 * KVPAD + 511) / 512, 512>>>();
    kv_kernel<<<dim3(ASPLITS, Bb), 512, A_TOT * sizeof(float)>>>(key, value, omega);
    out_kernel<<<dim3(Tt / 128, Bb), 512, B_TOT * sizeof(float)>>>(query, omega, out);
}

// round 8
// speedup vs baseline: 1.0225x; 1.0225x over previous
#include <cuda_runtime.h>
#include <math.h>
#include <stdint.h>

#define Bb 8
#define Tt 8192
#define Ss 8192
#define Ff 64
#define Dd 64
#define EPSf 1e-9f
#define KVPAD 72
#define ASPLITS 16
#define AROWS (Ss/ASPLITS)   /* 512 rows per block in kv kernel */

// kv scratch [b][256][72]; cols 65..71 stay zero
__device__ __align__(16) float g_kv[Bb * 256 * KVPAD];

// ---------------------------------------------------------------------------
// helpers
// ---------------------------------------------------------------------------
__device__ __forceinline__ float ftf32(float x) {
    unsigned u;
    asm("cvt.rna.tf32.f32 %0, %1;" : "=r"(u) : "f"(x));
    return __uint_as_float(u);
}

// fast exp on fma/alu pipes (no MUFU). |rel err| ~1e-7 for x >= -80.
__device__ __forceinline__ float fexp(float x) {
    const float LOG2E = 1.4426950408889634f;
    float xc = fmaxf(x, -80.0f);                 // keep n<<23 in range
    float y  = fmaf(xc, LOG2E, 12582912.0f);     // + 0x1.8p23 -> rint in low bits
    int   n  = __float_as_int(y);                // low bits hold integer part
    float r  = y - 12582912.0f;                  // rint(xc * log2e)
    float f  = fmaf(xc, LOG2E, -r);              // frac in [-0.5, 0.5]
    float p  = 1.3333558146e-3f;
    p = fmaf(p, f, 9.6181291076e-3f);
    p = fmaf(p, f, 5.5504108664e-2f);
    p = fmaf(p, f, 2.4022650696e-1f);
    p = fmaf(p, f, 6.9314718056e-1f);
    p = fmaf(p, f, 1.0f);                        // 2^f
    return __int_as_float(__float_as_int(p) + (n << 23));
}

__device__ __forceinline__ void mma8(float4& d,
                                     float a0, float a1, float a2, float a3,
                                     float b0, float b1) {
    asm("mma.sync.aligned.m16n8k8.row.col.f32.tf32.tf32.f32 "
        "{%0,%1,%2,%3},{%4,%5,%6,%7},{%8,%9},{%0,%1,%2,%3};"
        : "+f"(d.x), "+f"(d.y), "+f"(d.z), "+f"(d.w)
        : "r"(__float_as_uint(a0)), "r"(__float_as_uint(a1)),
          "r"(__float_as_uint(a2)), "r"(__float_as_uint(a3)),
          "r"(__float_as_uint(b0)), "r"(__float_as_uint(b1)));
}

__global__ void zero_kv_kernel() {
    int i = blockIdx.x * blockDim.x + threadIdx.x;
    if (i < Bb * 256 * KVPAD) g_kv[i] = 0.0f;
}

// ---------------------------------------------------------------------------
// smem layouts (float offsets)
// ---------------------------------------------------------------------------
// kernel A
#define A_KS   0        /* [64][68]  */
#define A_VS   4352     /* [64][72]  */
#define A_PHT  8960     /* [256][68] */
#define A_OHI  26368    /* [128][68] */
#define A_OLO  35072    /* [128][68] */
#define A_SSH  43776    /* [64]      */
#define A_PRT  43840    /* [256]     */
#define A_TOT  44096
// kernel B
#define B_PHIQ 0        /* [128][260], aliases Qs/Ohi/Olo during phase 1 */
#define B_QS   0        /* [128][68]  */
#define B_OHI  8704     /* [128][68]  */
#define B_OLO  17408    /* [128][68]  */
#define B_KVS  33280    /* [256][72]  */
#define B_SSH  51712    /* [128]      */
#define B_PRT  51840    /* [256]      */
#define B_TOT  52096

extern __shared__ float sm[];

// ---------------------------------------------------------------------------
// Kernel A: fused  K -> phi_k -> kv partial (split-K over S, atomics)
// block: 256 thr / 8 warps.  Per 64-row chunk:
//   XW[64x128] = K_chunk . Omega^T   (split tf32: 3 mma passes)
//   PhT[256][64] = exp(+-XW - ss) + eps   (tf32-rounded, stored transposed)
//   acc[256x72] += PhT . V1_chunk
// ---------------------------------------------------------------------------
__global__ __launch_bounds__(256, 1)
void kv_kernel(const float* __restrict__ key,
               const float* __restrict__ value,
               const float* __restrict__ omega) {
    const int b   = blockIdx.y;
    const int tid = threadIdx.x;
    const int w   = tid >> 5;
    const int ln  = tid & 31;
    const int gid = ln >> 2;
    const int tq  = ln & 3;

    float* Ks  = sm + A_KS;
    float* Vs  = sm + A_VS;
    float* PhT = sm + A_PHT;
    float* Ohi = sm + A_OHI;
    float* Olo = sm + A_OLO;
    float* ssh = sm + A_SSH;
    float* prt = sm + A_PRT;

    // omega -> hi/lo tf32 split in smem
    for (int i = tid; i < 128 * 64; i += 256) {
        int m = i >> 6, f = i & 63;
        float x  = omega[i];
        float hi = ftf32(x);
        Ohi[m * 68 + f] = hi;
        Olo[m * 68 + f] = ftf32(x - hi);
    }

    float4 acc[2][9];
    #pragma unroll
    for (int mt = 0; mt < 2; mt++)
        #pragma unroll
        for (int nt = 0; nt < 9; nt++)
            acc[mt][nt] = make_float4(0.f, 0.f, 0.f, 0.f);

    const int row0base = blockIdx.x * AROWS;

    for (int c = 0; c < AROWS / 64; c++) {
        __syncthreads();   // previous-iter PhT reads done before overwrite
        const int row0 = row0base + c * 64;

        // ---- load K chunk (+ssq partials) and V chunk (tf32, +ones col) ----
        {
            int r = tid >> 2, qd = tid & 3;
            const float4* kg = (const float4*)(key + ((size_t)(b * Ss + row0 + r)) * Ff);
            float ps = 0.f;
            #pragma unroll
            for (int j = 0; j < 4; j++) {
                float4 x = kg[qd * 4 + j];
                ps += x.x * x.x + x.y * x.y + x.z * x.z + x.w * x.w;
                ((float4*)(Ks + r * 68))[qd * 4 + j] = x;
            }
            prt[tid] = ps;
            const float4* vg = (const float4*)(value + ((size_t)(b * Ss + row0 + r)) * Dd);
            #pragma unroll
            for (int j = 0; j < 4; j++) {
                float4 x = vg[qd * 4 + j];
                float4 y;
                y.x = ftf32(x.x); y.y = ftf32(x.y); y.z = ftf32(x.z); y.w = ftf32(x.w);
                ((float4*)(Vs + r * 72))[qd * 4 + j] = y;
            }
            if (tid < 64) {
                Vs[tid * 72 + 64] = 1.0f;
                #pragma unroll
                for (int p = 65; p < 72; p++) Vs[tid * 72 + p] = 0.0f;
            }
        }
        __syncthreads();
        if (tid < 64)
            ssh[tid] = 0.5f * (prt[tid * 4] + prt[tid * 4 + 1] +
                               prt[tid * 4 + 2] + prt[tid * 4 + 3]);
        __syncthreads();

        // ---- XW = K . Omega^T  (M=64 s-rows, warp w owns features [16w,16w+16)) ----
        float4 xw[4][2];
        #pragma unroll
        for (int mt = 0; mt < 4; mt++)
            #pragma unroll
            for (int nt = 0; nt < 2; nt++)
                xw[mt][nt] = make_float4(0.f, 0.f, 0.f, 0.f);

        for (int ks = 0; ks < 8; ks++) {
            int f0 = ks * 8 + tq;
            float bh[2][2], bl[2][2];
            #pragma unroll
            for (int nt = 0; nt < 2; nt++) {
                int m = w * 16 + nt * 8 + gid;
                bh[nt][0] = Ohi[m * 68 + f0];     bh[nt][1] = Ohi[m * 68 + f0 + 4];
                bl[nt][0] = Olo[m * 68 + f0];     bl[nt][1] = Olo[m * 68 + f0 + 4];
            }
            #pragma unroll
            for (int mt = 0; mt < 4; mt++) {
                int s = mt * 16 + gid;
                float a0 = Ks[s * 68 + f0],       a1 = Ks[(s + 8) * 68 + f0];
                float a2 = Ks[s * 68 + f0 + 4],   a3 = Ks[(s + 8) * 68 + f0 + 4];
                float h0 = ftf32(a0), h1 = ftf32(a1), h2 = ftf32(a2), h3 = ftf32(a3);
                float l0 = ftf32(a0 - h0), l1 = ftf32(a1 - h1);
                float l2 = ftf32(a2 - h2), l3 = ftf32(a3 - h3);
                #pragma unroll
                for (int nt = 0; nt < 2; nt++) {
                    mma8(xw[mt][nt], h0, h1, h2, h3, bh[nt][0], bh[nt][1]);
                    mma8(xw[mt][nt], l0, l1, l2, l3, bh[nt][0], bh[nt][1]);
                    mma8(xw[mt][nt], h0, h1, h2, h3, bl[nt][0], bl[nt][1]);
                }
            }
        }

        // ---- phi epilogue: PhT[m][s] = tf32(fexp(+-xw - ss) + eps) ----
        #pragma unroll
        for (int mt = 0; mt < 4; mt++) {
            int s0 = mt * 16 + gid;
            float ssa = ssh[s0], ssb = ssh[s0 + 8];
            #pragma unroll
            for (int nt = 0; nt < 2; nt++) {
                int m0 = w * 16 + nt * 8 + 2 * tq;
                float4 v = xw[mt][nt];
                PhT[m0 * 68 + s0]             = ftf32(fexp( v.x - ssa) + EPSf);
                PhT[(m0 + 1) * 68 + s0]       = ftf32(fexp( v.y - ssa) + EPSf);
                PhT[m0 * 68 + s0 + 8]         = ftf32(fexp( v.z - ssb) + EPSf);
                PhT[(m0 + 1) * 68 + s0 + 8]   = ftf32(fexp( v.w - ssb) + EPSf);
                PhT[(m0 + 128) * 68 + s0]     = ftf32(fexp(-v.x - ssa) + EPSf);
                PhT[(m0 + 129) * 68 + s0]     = ftf32(fexp(-v.y - ssa) + EPSf);
                PhT[(m0 + 128) * 68 + s0 + 8] = ftf32(fexp(-v.z - ssb) + EPSf);
                PhT[(m0 + 129) * 68 + s0 + 8] = ftf32(fexp(-v.w - ssb) + EPSf);
            }
        }
        __syncthreads();

        // ---- acc += PhT . V1   (warp w owns kv rows [32w, 32w+32)) ----
        #pragma unroll 2
        for (int ks = 0; ks < 8; ks++) {
            float a[2][4];
            #pragma unroll
            for (int mt = 0; mt < 2; mt++) {
                int mr = 32 * w + mt * 16 + gid;
                int sc = ks * 8 + tq;
                a[mt][0] = PhT[mr * 68 + sc];
                a[mt][1] = PhT[(mr + 8) * 68 + sc];
                a[mt][2] = PhT[mr * 68 + sc + 4];
                a[mt][3] = PhT[(mr + 8) * 68 + sc + 4];
            }
            #pragma unroll
            for (int nt = 0; nt < 9; nt++) {
                float b0 = Vs[(ks * 8 + tq) * 72 + nt * 8 + gid];
                float b1 = Vs[(ks * 8 + tq + 4) * 72 + nt * 8 + gid];
                #pragma unroll
                for (int mt = 0; mt < 2; mt++)
                    mma8(acc[mt][nt], a[mt][0], a[mt][1], a[mt][2], a[mt][3], b0, b1);
            }
        }
    }

    // ---- atomic reduce into g_kv ----
    float* gp = g_kv + (size_t)b * 256 * KVPAD;
    #pragma unroll
    for (int mt = 0; mt < 2; mt++) {
        int m0 = 32 * w + mt * 16 + gid;
        #pragma unroll
        for (int nt = 0; nt < 9; nt++) {
            int d0 = nt * 8 + 2 * tq;
            atomicAdd(gp + m0 * KVPAD + d0,           acc[mt][nt].x);
            atomicAdd(gp + m0 * KVPAD + d0 + 1,       acc[mt][nt].y);
            atomicAdd(gp + (m0 + 8) * KVPAD + d0,     acc[mt][nt].z);
            atomicAdd(gp + (m0 + 8) * KVPAD + d0 + 1, acc[mt][nt].w);
        }
    }
}

// ---------------------------------------------------------------------------
// Kernel B: fused  Q -> phi_q -> out = (phi_q . kv) / normalizer
// block: 256 thr / 8 warps, 128 t-rows per block.
// ---------------------------------------------------------------------------
__global__ __launch_bounds__(256, 1)
void out_kernel(const float* __restrict__ query,
                const float* __restrict__ omega,
                float* __restrict__ outp) {
    const int b   = blockIdx.y;
    const int t0  = blockIdx.x * 128;
    const int tid = threadIdx.x;
    const int w   = tid >> 5;
    const int ln  = tid & 31;
    const int gid = ln >> 2;
    const int tq  = ln & 3;

    float* PhiQ = sm + B_PHIQ;
    float* Qs   = sm + B_QS;
    float* Ohi  = sm + B_OHI;
    float* Olo  = sm + B_OLO;
    float* kvs  = sm + B_KVS;
    float* ssh  = sm + B_SSH;
    float* prt  = sm + B_PRT;

    // ---- phase-1 loads: Q tile, omega hi/lo, kv (tf32-rounded) ----
    {
        int r = tid >> 1, h = tid & 1;
        const float4* qg = (const float4*)(query + ((size_t)(b * Tt + t0 + r)) * Ff);
        float ps = 0.f;
        #pragma unroll
        for (int j = 0; j < 8; j++) {
            float4 x = qg[h * 8 + j];
            ps += x.x * x.x + x.y * x.y + x.z * x.z + x.w * x.w;
            ((float4*)(Qs + r * 68))[h * 8 + j] = x;
        }
        prt[tid] = ps;
    }
    for (int i = tid; i < 128 * 64; i += 256) {
        int m = i >> 6, f = i & 63;
        float x  = omega[i];
        float hi = ftf32(x);
        Ohi[m * 68 + f] = hi;
        Olo[m * 68 + f] = ftf32(x - hi);
    }
    {
        const float4* gk = (const float4*)(g_kv + (size_t)b * 256 * KVPAD);
        for (int i = tid; i < 256 * KVPAD / 4; i += 256) {
            float4 x = gk[i];
            float4 y;
            y.x = ftf32(x.x); y.y = ftf32(x.y); y.z = ftf32(x.z); y.w = ftf32(x.w);
            ((float4*)kvs)[i] = y;
        }
    }
    __syncthreads();
    if (tid < 128) ssh[tid] = 0.5f * (prt[2 * tid] + prt[2 * tid + 1]);
    __syncthreads();

    // ---- XW = Q . Omega^T  (M=128 t-rows, warp w owns features [16w,16w+16)) ----
    float4 xw[8][2];
    #pragma unroll
    for (int mt = 0; mt < 8; mt++)
        #pragma unroll
        for (int nt = 0; nt < 2; nt++)
            xw[mt][nt] = make_float4(0.f, 0.f, 0.f, 0.f);

    for (int ks = 0; ks < 8; ks++) {
        int f0 = ks * 8 + tq;
        float bh[2][2], bl[2][2];
        #pragma unroll
        for (int nt = 0; nt < 2; nt++) {
            int m = w * 16 + nt * 8 + gid;
            bh[nt][0] = Ohi[m * 68 + f0];   bh[nt][1] = Ohi[m * 68 + f0 + 4];
            bl[nt][0] = Olo[m * 68 + f0];   bl[nt][1] = Olo[m * 68 + f0 + 4];
        }
        #pragma unroll
        for (int mt = 0; mt < 8; mt++) {
            int t = mt * 16 + gid;
            float a0 = Qs[t * 68 + f0],       a1 = Qs[(t + 8) * 68 + f0];
            float a2 = Qs[t * 68 + f0 + 4],   a3 = Qs[(t + 8) * 68 + f0 + 4];
            float h0 = ftf32(a0), h1 = ftf32(a1), h2 = ftf32(a2), h3 = ftf32(a3);
            float l0 = ftf32(a0 - h0), l1 = ftf32(a1 - h1);
            float l2 = ftf32(a2 - h2), l3 = ftf32(a3 - h3);
            #pragma unroll
            for (int nt = 0; nt < 2; nt++) {
                mma8(xw[mt][nt], h0, h1, h2, h3, bh[nt][0], bh[nt][1]);
                mma8(xw[mt][nt], l0, l1, l2, l3, bh[nt][0], bh[nt][1]);
                mma8(xw[mt][nt], h0, h1, h2, h3, bl[nt][0], bl[nt][1]);
            }
        }
    }
    __syncthreads();   // all Qs/omega reads done; PhiQ may overwrite them now

    // ---- phi epilogue: PhiQ[t][m] = tf32(fexp(+-xw - ss) + eps) ----
    #pragma unroll
    for (int mt = 0; mt < 8; mt++) {
        int t = mt * 16 + gid;
        float ssa = ssh[t], ssb = ssh[t + 8];
        #pragma unroll
        for (int nt = 0; nt < 2; nt++) {
            int m0 = w * 16 + nt * 8 + 2 * tq;
            float4 v = xw[mt][nt];
            PhiQ[t * 260 + m0]             = ftf32(fexp( v.x - ssa) + EPSf);
            PhiQ[t * 260 + m0 + 1]         = ftf32(fexp( v.y - ssa) + EPSf);
            PhiQ[(t + 8) * 260 + m0]       = ftf32(fexp( v.z - ssb) + EPSf);
            PhiQ[(t + 8) * 260 + m0 + 1]   = ftf32(fexp( v.w - ssb) + EPSf);
            PhiQ[t * 260 + m0 + 128]       = ftf32(fexp(-v.x - ssa) + EPSf);
            PhiQ[t * 260 + m0 + 129]       = ftf32(fexp(-v.y - ssa) + EPSf);
            PhiQ[(t + 8) * 260 + m0 + 128] = ftf32(fexp(-v.z - ssb) + EPSf);
            PhiQ[(t + 8) * 260 + m0 + 129] = ftf32(fexp(-v.w - ssb) + EPSf);
        }
    }
    __syncthreads();

    // ---- out = PhiQ . kv  (warp w owns t-rows [16w,16w+16), K=256) ----
    float4 oacc[9];
    #pragma unroll
    for (int nt = 0; nt < 9; nt++) oacc[nt] = make_float4(0.f, 0.f, 0.f, 0.f);

    #pragma unroll 4
    for (int ks = 0; ks < 32; ks++) {
        int tr = 16 * w + gid;
        int mc = ks * 8 + tq;
        float a0 = PhiQ[tr * 260 + mc],       a1 = PhiQ[(tr + 8) * 260 + mc];
        float a2 = PhiQ[tr * 260 + mc + 4],   a3 = PhiQ[(tr + 8) * 260 + mc + 4];
        #pragma unroll
        for (int nt = 0; nt < 9; nt++) {
            float b0 = kvs[(ks * 8 + tq) * KVPAD + nt * 8 + gid];
            float b1 = kvs[(ks * 8 + tq + 4) * KVPAD + nt * 8 + gid];
            mma8(oacc[nt], a0, a1, a2, a3, b0, b1);
        }
    }

    // ---- normalize (normalizer col 64 lives in n-tile 8, lanes tq==0) ----
    float n0 = __shfl_sync(0xffffffffu, oacc[8].x, ln & ~3);
    float n1 = __shfl_sync(0xffffffffu, oacc[8].z, ln & ~3);
    float inv0 = 1.0f / n0;
    float inv1 = 1.0f / n1;

    size_t orow = ((size_t)b * Tt + t0 + 16 * w + gid) * 64;
    #pragma unroll
    for (int nt = 0; nt < 8; nt++) {
        int col = nt * 8 + 2 * tq;
        float2 r0 = make_float2(oacc[nt].x * inv0, oacc[nt].y * inv0);
        float2 r1 = make_float2(oacc[nt].z * inv1, oacc[nt].w * inv1);
        *(float2*)(outp + orow + col)          = r0;
        *(float2*)(outp + orow + 8 * 64 + col) = r1;
    }
}

// ---------------------------------------------------------------------------
// launch
// ---------------------------------------------------------------------------
extern "C" void kernel_launch(void* const* d_in, const int* in_sizes, int n_in,
                              void* d_out, int out_size) {
    const float* query = (const float*)d_in[0];
    const float* value = (const float*)d_in[1];
    const float* key   = (const float*)d_in[2];
    const float* omega = (const float*)d_in[3];
    float* out = (float*)d_out;

    cudaFuncSetAttribute(kv_kernel,  cudaFuncAttributeMaxDynamicSharedMemorySize,
                         A_TOT * (int)sizeof(float));
    cudaFuncSetAttribute(out_kernel, cudaFuncAttributeMaxDynamicSharedMemorySize,
                         B_TOT * (int)sizeof(float));

    zero_kv_kernel<<<(Bb * 256 * KVPAD + 255) / 256, 256>>>();
    kv_kernel<<<dim3(ASPLITS, Bb), 256, A_TOT * sizeof(float)>>>(key, value, omega);
    out_kernel<<<dim3(Tt / 128, Bb), 256, B_TOT * sizeof(float)>>>(query, omega, out);
}

// round 9
// speedup vs baseline: 1.2809x; 1.2527x over previous
#include <cuda_runtime.h>
#include <cuda_bf16.h>
#include <math.h>
#include <stdint.h>

#define Bb 8
#define Tt 8192
#define Ss 8192
#define Ff 64
#define Dd 64
#define EPSf 1e-9f
#define KVPAD 72
#define ASPLITS 16
#define AROWS (Ss/ASPLITS)   /* 512 rows per block in kv kernel */

// kv scratch [b][256][72]; cols 65..71 stay zero
__device__ __align__(16) float g_kv[Bb * 256 * KVPAD];

// ---------------------------------------------------------------------------
// helpers
// ---------------------------------------------------------------------------
__device__ __forceinline__ float ftf32(float x) {
    unsigned u;
    asm("cvt.rna.tf32.f32 %0, %1;" : "=r"(u) : "f"(x));
    return __uint_as_float(u);
}

// pack two floats to bf16x2 (lo = x0, hi = x1), round-to-nearest
__device__ __forceinline__ uint32_t packbf(float x0, float x1) {
    uint32_t u;
    asm("cvt.rn.bf16x2.f32 %0, %1, %2;" : "=r"(u) : "f"(x1), "f"(x0));
    return u;
}

// split pair (x0,x1) into bf16 hi word and bf16 lo (residual) word
__device__ __forceinline__ void split2(float x0, float x1,
                                       uint32_t& hw, uint32_t& lw) {
    float h0 = __bfloat162float(__float2bfloat16(x0));
    float h1 = __bfloat162float(__float2bfloat16(x1));
    hw = packbf(x0, x1);
    lw = packbf(x0 - h0, x1 - h1);
}

// tf32 m16n8k8 (GEMM3/GEMM4)
__device__ __forceinline__ void mma8(float4& d,
                                     float a0, float a1, float a2, float a3,
                                     float b0, float b1) {
    asm("mma.sync.aligned.m16n8k8.row.col.f32.tf32.tf32.f32 "
        "{%0,%1,%2,%3},{%4,%5,%6,%7},{%8,%9},{%0,%1,%2,%3};"
        : "+f"(d.x), "+f"(d.y), "+f"(d.z), "+f"(d.w)
        : "r"(__float_as_uint(a0)), "r"(__float_as_uint(a1)),
          "r"(__float_as_uint(a2)), "r"(__float_as_uint(a3)),
          "r"(__float_as_uint(b0)), "r"(__float_as_uint(b1)));
}

// bf16 m16n8k16 (GEMM1)
__device__ __forceinline__ void mma16(float4& d,
                                      uint32_t a0, uint32_t a1,
                                      uint32_t a2, uint32_t a3,
                                      uint32_t b0, uint32_t b1) {
    asm("mma.sync.aligned.m16n8k16.row.col.f32.bf16.bf16.f32 "
        "{%0,%1,%2,%3},{%4,%5,%6,%7},{%8,%9},{%0,%1,%2,%3};"
        : "+f"(d.x), "+f"(d.y), "+f"(d.z), "+f"(d.w)
        : "r"(a0), "r"(a1), "r"(a2), "r"(a3), "r"(b0), "r"(b1));
}

__global__ void zero_kv_kernel() {
    int i = blockIdx.x * blockDim.x + threadIdx.x;
    if (i < Bb * 256 * KVPAD) g_kv[i] = 0.0f;
}

// ---------------------------------------------------------------------------
// smem layouts (32-bit word offsets). Packed bf16x2 arrays use stride 36
// words per 64-element row (conflict-free mma fragment reads: 36%32=4).
// ---------------------------------------------------------------------------
// kernel A
#define A_KHI   0        /* [64][36]  packed bf16x2 hi */
#define A_KLO   2304     /* [64][36]  packed bf16x2 lo */
#define A_VS    4608     /* [64][72]  tf32 floats      */
#define A_PHT   9216     /* [256][68] tf32 floats      */
#define A_OHIP  26624    /* [128][36] packed hi        */
#define A_OLOP  31232    /* [128][36] packed lo        */
#define A_SSH   35840    /* [64]  */
#define A_PRT   35904    /* [256] */
#define A_TOT   36160
// kernel B
#define B_PHIQ  0        /* [128][260] floats, aliases packed arrays below */
#define B_QHI   0        /* [128][36] */
#define B_QLO   4608     /* [128][36] */
#define B_OHIP  9216     /* [128][36] */
#define B_OLOP  13824    /* [128][36] */
#define B_KVS   33280    /* [256][72] */
#define B_SSH   51712    /* [128] */
#define B_PRT   51840    /* [256] */
#define B_TOT   52096

extern __shared__ float sm[];

// ---------------------------------------------------------------------------
// Kernel A: fused  K -> phi_k -> kv partial (split-K over S, atomics)
// Per 64-row chunk:
//   XW[64x128] = K . Omega^T        (split-bf16, 3-pass m16n8k16)
//   PhT[256][64] = exp(+-XW - ss)   (tf32, transposed)
//   acc[256x72] += PhT . V1         (tf32 m16n8k8)
// ---------------------------------------------------------------------------
__global__ __launch_bounds__(256, 1)
void kv_kernel(const float* __restrict__ key,
               const float* __restrict__ value,
               const float* __restrict__ omega) {
    const int b   = blockIdx.y;
    const int tid = threadIdx.x;
    const int w   = tid >> 5;
    const int ln  = tid & 31;
    const int gid = ln >> 2;
    const int tq  = ln & 3;

    uint32_t* Khi = (uint32_t*)(sm + A_KHI);
    uint32_t* Klo = (uint32_t*)(sm + A_KLO);
    float*    Vs  = sm + A_VS;
    float*    PhT = sm + A_PHT;
    uint32_t* Ohp = (uint32_t*)(sm + A_OHIP);
    uint32_t* Olp = (uint32_t*)(sm + A_OLOP);
    float*    ssh = sm + A_SSH;
    float*    prt = sm + A_PRT;

    // omega -> packed bf16 hi/lo split in smem (once)
    for (int i = tid; i < 128 * 32; i += 256) {
        int m = i >> 5, wj = i & 31;
        uint32_t hw, lw;
        split2(omega[m * 64 + 2 * wj], omega[m * 64 + 2 * wj + 1], hw, lw);
        Ohp[m * 36 + wj] = hw;
        Olp[m * 36 + wj] = lw;
    }

    float4 acc[2][9];
    #pragma unroll
    for (int mt = 0; mt < 2; mt++)
        #pragma unroll
        for (int nt = 0; nt < 9; nt++)
            acc[mt][nt] = make_float4(0.f, 0.f, 0.f, 0.f);

    const int row0base = blockIdx.x * AROWS;

    for (int c = 0; c < AROWS / 64; c++) {
        __syncthreads();   // previous-iter PhT/tile reads done before overwrite
        const int row0 = row0base + c * 64;

        // ---- load K chunk (split to bf16 hi/lo, +ssq) and V chunk (tf32) ----
        {
            int r = tid >> 2, qd = tid & 3;
            const float4* kg = (const float4*)(key + ((size_t)(b * Ss + row0 + r)) * Ff);
            float ps = 0.f;
            #pragma unroll
            for (int j = 0; j < 4; j++) {
                int fj = qd * 4 + j;
                float4 x = kg[fj];
                ps += x.x * x.x + x.y * x.y + x.z * x.z + x.w * x.w;
                uint32_t hw, lw;
                split2(x.x, x.y, hw, lw);
                Khi[r * 36 + 2 * fj]     = hw;
                Klo[r * 36 + 2 * fj]     = lw;
                split2(x.z, x.w, hw, lw);
                Khi[r * 36 + 2 * fj + 1] = hw;
                Klo[r * 36 + 2 * fj + 1] = lw;
            }
            prt[tid] = ps;
            const float4* vg = (const float4*)(value + ((size_t)(b * Ss + row0 + r)) * Dd);
            #pragma unroll
            for (int j = 0; j < 4; j++) {
                float4 x = vg[qd * 4 + j];
                float4 y;
                y.x = ftf32(x.x); y.y = ftf32(x.y); y.z = ftf32(x.z); y.w = ftf32(x.w);
                ((float4*)(Vs + r * 72))[qd * 4 + j] = y;
            }
            if (tid < 64) {
                Vs[tid * 72 + 64] = 1.0f;
                #pragma unroll
                for (int p = 65; p < 72; p++) Vs[tid * 72 + p] = 0.0f;
            }
        }
        __syncthreads();
        if (tid < 64)
            ssh[tid] = 0.5f * (prt[tid * 4] + prt[tid * 4 + 1] +
                               prt[tid * 4 + 2] + prt[tid * 4 + 3]);
        __syncthreads();

        // ---- XW = K . Omega^T  (split-bf16 k16; warp w: features [16w,16w+16)) ----
        float4 xw[4][2];
        #pragma unroll
        for (int mt = 0; mt < 4; mt++)
            #pragma unroll
            for (int nt = 0; nt < 2; nt++)
                xw[mt][nt] = make_float4(0.f, 0.f, 0.f, 0.f);

        #pragma unroll
        for (int ks = 0; ks < 4; ks++) {
            int f0w = ks * 8 + tq;
            uint32_t bh[2][2], bl[2][2];
            #pragma unroll
            for (int nt = 0; nt < 2; nt++) {
                int m = w * 16 + nt * 8 + gid;
                bh[nt][0] = Ohp[m * 36 + f0w];  bh[nt][1] = Ohp[m * 36 + f0w + 4];
                bl[nt][0] = Olp[m * 36 + f0w];  bl[nt][1] = Olp[m * 36 + f0w + 4];
            }
            #pragma unroll
            for (int mt = 0; mt < 4; mt++) {
                int s = mt * 16 + gid;
                uint32_t ah0 = Khi[s * 36 + f0w];
                uint32_t ah1 = Khi[(s + 8) * 36 + f0w];
                uint32_t ah2 = Khi[s * 36 + f0w + 4];
                uint32_t ah3 = Khi[(s + 8) * 36 + f0w + 4];
                uint32_t al0 = Klo[s * 36 + f0w];
                uint32_t al1 = Klo[(s + 8) * 36 + f0w];
                uint32_t al2 = Klo[s * 36 + f0w + 4];
                uint32_t al3 = Klo[(s + 8) * 36 + f0w + 4];
                #pragma unroll
                for (int nt = 0; nt < 2; nt++) {
                    mma16(xw[mt][nt], ah0, ah1, ah2, ah3, bh[nt][0], bh[nt][1]);
                    mma16(xw[mt][nt], al0, al1, al2, al3, bh[nt][0], bh[nt][1]);
                    mma16(xw[mt][nt], ah0, ah1, ah2, ah3, bl[nt][0], bl[nt][1]);
                }
            }
        }

        // ---- phi epilogue: PhT[m][s] = tf32(exp(+-xw - ss) + eps) ----
        #pragma unroll
        for (int mt = 0; mt < 4; mt++) {
            int s0 = mt * 16 + gid;
            float ssa = ssh[s0], ssb = ssh[s0 + 8];
            #pragma unroll
            for (int nt = 0; nt < 2; nt++) {
                int m0 = w * 16 + nt * 8 + 2 * tq;
                float4 v = xw[mt][nt];
                PhT[m0 * 68 + s0]             = ftf32(__expf( v.x - ssa) + EPSf);
                PhT[(m0 + 1) * 68 + s0]       = ftf32(__expf( v.y - ssa) + EPSf);
                PhT[m0 * 68 + s0 + 8]         = ftf32(__expf( v.z - ssb) + EPSf);
                PhT[(m0 + 1) * 68 + s0 + 8]   = ftf32(__expf( v.w - ssb) + EPSf);
                PhT[(m0 + 128) * 68 + s0]     = ftf32(__expf(-v.x - ssa) + EPSf);
                PhT[(m0 + 129) * 68 + s0]     = ftf32(__expf(-v.y - ssa) + EPSf);
                PhT[(m0 + 128) * 68 + s0 + 8] = ftf32(__expf(-v.z - ssb) + EPSf);
                PhT[(m0 + 129) * 68 + s0 + 8] = ftf32(__expf(-v.w - ssb) + EPSf);
            }
        }
        __syncthreads();

        // ---- acc += PhT . V1   (tf32 k8; warp w owns kv rows [32w, 32w+32)) ----
        #pragma unroll 2
        for (int ks = 0; ks < 8; ks++) {
            float a[2][4];
            #pragma unroll
            for (int mt = 0; mt < 2; mt++) {
                int mr = 32 * w + mt * 16 + gid;
                int sc = ks * 8 + tq;
                a[mt][0] = PhT[mr * 68 + sc];
                a[mt][1] = PhT[(mr + 8) * 68 + sc];
                a[mt][2] = PhT[mr * 68 + sc + 4];
                a[mt][3] = PhT[(mr + 8) * 68 + sc + 4];
            }
            #pragma unroll
            for (int nt = 0; nt < 9; nt++) {
                float b0 = Vs[(ks * 8 + tq) * 72 + nt * 8 + gid];
                float b1 = Vs[(ks * 8 + tq + 4) * 72 + nt * 8 + gid];
                #pragma unroll
                for (int mt = 0; mt < 2; mt++)
                    mma8(acc[mt][nt], a[mt][0], a[mt][1], a[mt][2], a[mt][3], b0, b1);
            }
        }
    }

    // ---- atomic reduce into g_kv ----
    float* gp = g_kv + (size_t)b * 256 * KVPAD;
    #pragma unroll
    for (int mt = 0; mt < 2; mt++) {
        int m0 = 32 * w + mt * 16 + gid;
        #pragma unroll
        for (int nt = 0; nt < 9; nt++) {
            int d0 = nt * 8 + 2 * tq;
            atomicAdd(gp + m0 * KVPAD + d0,           acc[mt][nt].x);
            atomicAdd(gp + m0 * KVPAD + d0 + 1,       acc[mt][nt].y);
            atomicAdd(gp + (m0 + 8) * KVPAD + d0,     acc[mt][nt].z);
            atomicAdd(gp + (m0 + 8) * KVPAD + d0 + 1, acc[mt][nt].w);
        }
    }
}

// ---------------------------------------------------------------------------
// Kernel B: fused  Q -> phi_q -> out = (phi_q . kv) / normalizer
// GEMM1 split-bf16 k16; GEMM4 tf32 k8.
// ---------------------------------------------------------------------------
__global__ __launch_bounds__(256, 1)
void out_kernel(const float* __restrict__ query,
                const float* __restrict__ omega,
                float* __restrict__ outp) {
    const int b   = blockIdx.y;
    const int t0  = blockIdx.x * 128;
    const int tid = threadIdx.x;
    const int w   = tid >> 5;
    const int ln  = tid & 31;
    const int gid = ln >> 2;
    const int tq  = ln & 3;

    float*    PhiQ = sm + B_PHIQ;
    uint32_t* Qhi  = (uint32_t*)(sm + B_QHI);
    uint32_t* Qlo  = (uint32_t*)(sm + B_QLO);
    uint32_t* Ohp  = (uint32_t*)(sm + B_OHIP);
    uint32_t* Olp  = (uint32_t*)(sm + B_OLOP);
    float*    kvs  = sm + B_KVS;
    float*    ssh  = sm + B_SSH;
    float*    prt  = sm + B_PRT;

    // ---- phase-1 loads: Q (bf16 hi/lo split), omega split, kv (tf32) ----
    {
        int r = tid >> 1, h = tid & 1;
        const float4* qg = (const float4*)(query + ((size_t)(b * Tt + t0 + r)) * Ff);
        float ps = 0.f;
        #pragma unroll
        for (int jj = 0; jj < 8; jj++) {
            int fj = h * 8 + jj;
            float4 x = qg[fj];
            ps += x.x * x.x + x.y * x.y + x.z * x.z + x.w * x.w;
            uint32_t hw, lw;
            split2(x.x, x.y, hw, lw);
            Qhi[r * 36 + 2 * fj]     = hw;
            Qlo[r * 36 + 2 * fj]     = lw;
            split2(x.z, x.w, hw, lw);
            Qhi[r * 36 + 2 * fj + 1] = hw;
            Qlo[r * 36 + 2 * fj + 1] = lw;
        }
        prt[tid] = ps;
    }
    for (int i = tid; i < 128 * 32; i += 256) {
        int m = i >> 5, wj = i & 31;
        uint32_t hw, lw;
        split2(omega[m * 64 + 2 * wj], omega[m * 64 + 2 * wj + 1], hw, lw);
        Ohp[m * 36 + wj] = hw;
        Olp[m * 36 + wj] = lw;
    }
    {
        const float4* gk = (const float4*)(g_kv + (size_t)b * 256 * KVPAD);
        for (int i = tid; i < 256 * KVPAD / 4; i += 256) {
            float4 x = gk[i];
            float4 y;
            y.x = ftf32(x.x); y.y = ftf32(x.y); y.z = ftf32(x.z); y.w = ftf32(x.w);
            ((float4*)kvs)[i] = y;
        }
    }
    __syncthreads();
    if (tid < 128) ssh[tid] = 0.5f * (prt[2 * tid] + prt[2 * tid + 1]);
    __syncthreads();

    // ---- XW = Q . Omega^T  (split-bf16 k16; warp w: features [16w,16w+16)) ----
    float4 xw[8][2];
    #pragma unroll
    for (int mt = 0; mt < 8; mt++)
        #pragma unroll
        for (int nt = 0; nt < 2; nt++)
            xw[mt][nt] = make_float4(0.f, 0.f, 0.f, 0.f);

    #pragma unroll
    for (int ks = 0; ks < 4; ks++) {
        int f0w = ks * 8 + tq;
        uint32_t bh[2][2], bl[2][2];
        #pragma unroll
        for (int nt = 0; nt < 2; nt++) {
            int m = w * 16 + nt * 8 + gid;
            bh[nt][0] = Ohp[m * 36 + f0w];  bh[nt][1] = Ohp[m * 36 + f0w + 4];
            bl[nt][0] = Olp[m * 36 + f0w];  bl[nt][1] = Olp[m * 36 + f0w + 4];
        }
        #pragma unroll
        for (int mt = 0; mt < 8; mt++) {
            int t = mt * 16 + gid;
            uint32_t ah0 = Qhi[t * 36 + f0w];
            uint32_t ah1 = Qhi[(t + 8) * 36 + f0w];
            uint32_t ah2 = Qhi[t * 36 + f0w + 4];
            uint32_t ah3 = Qhi[(t + 8) * 36 + f0w + 4];
            uint32_t al0 = Qlo[t * 36 + f0w];
            uint32_t al1 = Qlo[(t + 8) * 36 + f0w];
            uint32_t al2 = Qlo[t * 36 + f0w + 4];
            uint32_t al3 = Qlo[(t + 8) * 36 + f0w + 4];
            #pragma unroll
            for (int nt = 0; nt < 2; nt++) {
                mma16(xw[mt][nt], ah0, ah1, ah2, ah3, bh[nt][0], bh[nt][1]);
                mma16(xw[mt][nt], al0, al1, al2, al3, bh[nt][0], bh[nt][1]);
                mma16(xw[mt][nt], ah0, ah1, ah2, ah3, bl[nt][0], bl[nt][1]);
            }
        }
    }
    __syncthreads();   // all Q/omega packed reads done; PhiQ may overwrite

    // ---- phi epilogue: PhiQ[t][m] = tf32(exp(+-xw - ss) + eps) ----
    #pragma unroll
    for (int mt = 0; mt < 8; mt++) {
        int t = mt * 16 + gid;
        float ssa = ssh[t], ssb = ssh[t + 8];
        #pragma unroll
        for (int nt = 0; nt < 2; nt++) {
            int m0 = w * 16 + nt * 8 + 2 * tq;
            float4 v = xw[mt][nt];
            PhiQ[t * 260 + m0]             = ftf32(__expf( v.x - ssa) + EPSf);
            PhiQ[t * 260 + m0 + 1]         = ftf32(__expf( v.y - ssa) + EPSf);
            PhiQ[(t + 8) * 260 + m0]       = ftf32(__expf( v.z - ssb) + EPSf);
            PhiQ[(t + 8) * 260 + m0 + 1]   = ftf32(__expf( v.w - ssb) + EPSf);
            PhiQ[t * 260 + m0 + 128]       = ftf32(__expf(-v.x - ssa) + EPSf);
            PhiQ[t * 260 + m0 + 129]       = ftf32(__expf(-v.y - ssa) + EPSf);
            PhiQ[(t + 8) * 260 + m0 + 128] = ftf32(__expf(-v.z - ssb) + EPSf);
            PhiQ[(t + 8) * 260 + m0 + 129] = ftf32(__expf(-v.w - ssb) + EPSf);
        }
    }
    __syncthreads();

    // ---- out = PhiQ . kv  (tf32 k8; warp w owns t-rows [16w,16w+16)) ----
    float4 oacc[9];
    #pragma unroll
    for (int nt = 0; nt < 9; nt++) oacc[nt] = make_float4(0.f, 0.f, 0.f, 0.f);

    #pragma unroll 4
    for (int ks = 0; ks < 32; ks++) {
        int tr = 16 * w + gid;
        int mc = ks * 8 + tq;
        float a0 = PhiQ[tr * 260 + mc],       a1 = PhiQ[(tr + 8) * 260 + mc];
        float a2 = PhiQ[tr * 260 + mc + 4],   a3 = PhiQ[(tr + 8) * 260 + mc + 4];
        #pragma unroll
        for (int nt = 0; nt < 9; nt++) {
            float b0 = kvs[(ks * 8 + tq) * KVPAD + nt * 8 + gid];
            float b1 = kvs[(ks * 8 + tq + 4) * KVPAD + nt * 8 + gid];
            mma8(oacc[nt], a0, a1, a2, a3, b0, b1);
        }
    }

    // ---- normalize (normalizer col 64 lives in n-tile 8, lanes tq==0) ----
    float n0 = __shfl_sync(0xffffffffu, oacc[8].x, ln & ~3);
    float n1 = __shfl_sync(0xffffffffu, oacc[8].z, ln & ~3);
    float inv0 = 1.0f / n0;
    float inv1 = 1.0f / n1;

    size_t orow = ((size_t)b * Tt + t0 + 16 * w + gid) * 64;
    #pragma unroll
    for (int nt = 0; nt < 8; nt++) {
        int col = nt * 8 + 2 * tq;
        float2 r0 = make_float2(oacc[nt].x * inv0, oacc[nt].y * inv0);
        float2 r1 = make_float2(oacc[nt].z * inv1, oacc[nt].w * inv1);
        *(float2*)(outp + orow + col)          = r0;
        *(float2*)(outp + orow + 8 * 64 + col) = r1;
    }
}

// ---------------------------------------------------------------------------
// launch
// ---------------------------------------------------------------------------
extern "C" void kernel_launch(void* const* d_in, const int* in_sizes, int n_in,
                              void* d_out, int out_size) {
    const float* query = (const float*)d_in[0];
    const float* value = (const float*)d_in[1];
    const float* key   = (const float*)d_in[2];
    const float* omega = (const float*)d_in[3];
    float* out = (float*)d_out;

    cudaFuncSetAttribute(kv_kernel,  cudaFuncAttributeMaxDynamicSharedMemorySize,
                         A_TOT * (int)sizeof(float));
    cudaFuncSetAttribute(out_kernel, cudaFuncAttributeMaxDynamicSharedMemorySize,
                         B_TOT * (int)sizeof(float));

    zero_kv_kernel<<<(Bb * 256 * KVPAD + 255) / 256, 256>>>();
    kv_kernel<<<dim3(ASPLITS, Bb), 256, A_TOT * sizeof(float)>>>(key, value, omega);
    out_kernel<<<dim3(Tt / 128, Bb), 256, B_TOT * sizeof(float)>>>(query, omega, out);
}

// round 10
// speedup vs baseline: 1.2819x; 1.0008x over previous
#include <cuda_runtime.h>
#include <cuda_bf16.h>
#include <math.h>
#include <stdint.h>

#define Bb 8
#define Tt 8192
#define Ss 8192
#define Ff 64
#define Dd 64
#define EPSf 1e-9f
#define KVPAD 72
#define ASPLITS 16
#define AROWS (Ss/ASPLITS)   /* 512 rows per block in kv kernel */

// kv scratch [b][256][72]; cols 65..71 stay zero
__device__ __align__(16) float g_kv[Bb * 256 * KVPAD];

// ---------------------------------------------------------------------------
// helpers
// ---------------------------------------------------------------------------
__device__ __forceinline__ float ftf32(float x) {
    unsigned u;
    asm("cvt.rna.tf32.f32 %0, %1;" : "=r"(u) : "f"(x));
    return __uint_as_float(u);
}

// pack two floats to bf16x2 (lo = x0, hi = x1), round-to-nearest
__device__ __forceinline__ uint32_t packbf(float x0, float x1) {
    uint32_t u;
    asm("cvt.rn.bf16x2.f32 %0, %1, %2;" : "=r"(u) : "f"(x1), "f"(x0));
    return u;
}

// split pair (x0,x1) into bf16 hi word and bf16 lo (residual) word
__device__ __forceinline__ void split2(float x0, float x1,
                                       uint32_t& hw, uint32_t& lw) {
    float h0 = __bfloat162float(__float2bfloat16(x0));
    float h1 = __bfloat162float(__float2bfloat16(x1));
    hw = packbf(x0, x1);
    lw = packbf(x0 - h0, x1 - h1);
}

// tf32 m16n8k8 (GEMM3/GEMM4)
__device__ __forceinline__ void mma8(float4& d,
                                     float a0, float a1, float a2, float a3,
                                     float b0, float b1) {
    asm("mma.sync.aligned.m16n8k8.row.col.f32.tf32.tf32.f32 "
        "{%0,%1,%2,%3},{%4,%5,%6,%7},{%8,%9},{%0,%1,%2,%3};"
        : "+f"(d.x), "+f"(d.y), "+f"(d.z), "+f"(d.w)
        : "r"(__float_as_uint(a0)), "r"(__float_as_uint(a1)),
          "r"(__float_as_uint(a2)), "r"(__float_as_uint(a3)),
          "r"(__float_as_uint(b0)), "r"(__float_as_uint(b1)));
}

// bf16 m16n8k16 (GEMM1)
__device__ __forceinline__ void mma16(float4& d,
                                      uint32_t a0, uint32_t a1,
                                      uint32_t a2, uint32_t a3,
                                      uint32_t b0, uint32_t b1) {
    asm("mma.sync.aligned.m16n8k16.row.col.f32.bf16.bf16.f32 "
        "{%0,%1,%2,%3},{%4,%5,%6,%7},{%8,%9},{%0,%1,%2,%3};"
        : "+f"(d.x), "+f"(d.y), "+f"(d.z), "+f"(d.w)
        : "r"(a0), "r"(a1), "r"(a2), "r"(a3), "r"(b0), "r"(b1));
}

__global__ void zero_kv_kernel() {
    int i = blockIdx.x * blockDim.x + threadIdx.x;
    if (i < Bb * 256 * KVPAD) g_kv[i] = 0.0f;
}

// ---------------------------------------------------------------------------
// smem layouts (32-bit word offsets). Packed bf16x2 arrays use stride 36
// words per 64-element row (conflict-free mma fragment reads: 36%32=4).
// ---------------------------------------------------------------------------
// kernel A
#define A_KHI   0        /* [64][36]  packed bf16x2 hi */
#define A_KLO   2304     /* [64][36]  packed bf16x2 lo */
#define A_VS    4608     /* [64][72]  tf32 floats      */
#define A_PHT   9216     /* [256][68] tf32 floats      */
#define A_OHIP  26624    /* [128][36] packed hi        */
#define A_OLOP  31232    /* [128][36] packed lo        */
#define A_SSH   35840    /* [64]  */
#define A_PRT   35904    /* [256] */
#define A_TOT   36160
// kernel B
#define B_PHIQ  0        /* [128][260] floats, aliases packed arrays below */
#define B_QHI   0        /* [128][36] */
#define B_QLO   4608     /* [128][36] */
#define B_OHIP  9216     /* [128][36] */
#define B_OLOP  13824    /* [128][36] */
#define B_KVS   33280    /* [256][72] */
#define B_SSH   51712    /* [128] */
#define B_PRT   51840    /* [256] */
#define B_TOT   52096

extern __shared__ float sm[];

// ---------------------------------------------------------------------------
// Kernel A: fused  K -> phi_k -> kv partial (split-K over S, atomics)
// Per 64-row chunk:
//   XW[64x128] = K . Omega^T        (split-bf16, 3-pass m16n8k16)
//   PhT[256][64] = exp(+-XW - ss)   (tf32, transposed)
//   acc[256x72] += PhT . V1         (tf32 m16n8k8)
// ---------------------------------------------------------------------------
__global__ __launch_bounds__(256, 1)
void kv_kernel(const float* __restrict__ key,
               const float* __restrict__ value,
               const float* __restrict__ omega) {
    const int b   = blockIdx.y;
    const int tid = threadIdx.x;
    const int w   = tid >> 5;
    const int ln  = tid & 31;
    const int gid = ln >> 2;
    const int tq  = ln & 3;

    uint32_t* Khi = (uint32_t*)(sm + A_KHI);
    uint32_t* Klo = (uint32_t*)(sm + A_KLO);
    float*    Vs  = sm + A_VS;
    float*    PhT = sm + A_PHT;
    uint32_t* Ohp = (uint32_t*)(sm + A_OHIP);
    uint32_t* Olp = (uint32_t*)(sm + A_OLOP);
    float*    ssh = sm + A_SSH;
    float*    prt = sm + A_PRT;

    // omega -> packed bf16 hi/lo split in smem (once)
    for (int i = tid; i < 128 * 32; i += 256) {
        int m = i >> 5, wj = i & 31;
        uint32_t hw, lw;
        split2(omega[m * 64 + 2 * wj], omega[m * 64 + 2 * wj + 1], hw, lw);
        Ohp[m * 36 + wj] = hw;
        Olp[m * 36 + wj] = lw;
    }

    float4 acc[2][9];
    #pragma unroll
    for (int mt = 0; mt < 2; mt++)
        #pragma unroll
        for (int nt = 0; nt < 9; nt++)
            acc[mt][nt] = make_float4(0.f, 0.f, 0.f, 0.f);

    const int row0base = blockIdx.x * AROWS;

    for (int c = 0; c < AROWS / 64; c++) {
        __syncthreads();   // previous-iter PhT/tile reads done before overwrite
        const int row0 = row0base + c * 64;

        // ---- load K chunk (split to bf16 hi/lo, +ssq) and V chunk (tf32) ----
        {
            int r = tid >> 2, qd = tid & 3;
            const float4* kg = (const float4*)(key + ((size_t)(b * Ss + row0 + r)) * Ff);
            float ps = 0.f;
            #pragma unroll
            for (int j = 0; j < 4; j++) {
                int fj = qd * 4 + j;
                float4 x = kg[fj];
                ps += x.x * x.x + x.y * x.y + x.z * x.z + x.w * x.w;
                uint32_t hw, lw;
                split2(x.x, x.y, hw, lw);
                Khi[r * 36 + 2 * fj]     = hw;
                Klo[r * 36 + 2 * fj]     = lw;
                split2(x.z, x.w, hw, lw);
                Khi[r * 36 + 2 * fj + 1] = hw;
                Klo[r * 36 + 2 * fj + 1] = lw;
            }
            prt[tid] = ps;
            const float4* vg = (const float4*)(value + ((size_t)(b * Ss + row0 + r)) * Dd);
            #pragma unroll
            for (int j = 0; j < 4; j++) {
                float4 x = vg[qd * 4 + j];
                float4 y;
                y.x = ftf32(x.x); y.y = ftf32(x.y); y.z = ftf32(x.z); y.w = ftf32(x.w);
                ((float4*)(Vs + r * 72))[qd * 4 + j] = y;
            }
            if (tid < 64) {
                Vs[tid * 72 + 64] = 1.0f;
                #pragma unroll
                for (int p = 65; p < 72; p++) Vs[tid * 72 + p] = 0.0f;
            }
        }
        __syncthreads();
        if (tid < 64)
            ssh[tid] = 0.5f * (prt[tid * 4] + prt[tid * 4 + 1] +
                               prt[tid * 4 + 2] + prt[tid * 4 + 3]);
        __syncthreads();

        // ---- XW = K . Omega^T  (split-bf16 k16; warp w: features [16w,16w+16)) ----
        float4 xw[4][2];
        #pragma unroll
        for (int mt = 0; mt < 4; mt++)
            #pragma unroll
            for (int nt = 0; nt < 2; nt++)
                xw[mt][nt] = make_float4(0.f, 0.f, 0.f, 0.f);

        #pragma unroll
        for (int ks = 0; ks < 4; ks++) {
            int f0w = ks * 8 + tq;
            uint32_t bh[2][2], bl[2][2];
            #pragma unroll
            for (int nt = 0; nt < 2; nt++) {
                int m = w * 16 + nt * 8 + gid;
                bh[nt][0] = Ohp[m * 36 + f0w];  bh[nt][1] = Ohp[m * 36 + f0w + 4];
                bl[nt][0] = Olp[m * 36 + f0w];  bl[nt][1] = Olp[m * 36 + f0w + 4];
            }
            #pragma unroll
            for (int mt = 0; mt < 4; mt++) {
                int s = mt * 16 + gid;
                uint32_t ah0 = Khi[s * 36 + f0w];
                uint32_t ah1 = Khi[(s + 8) * 36 + f0w];
                uint32_t ah2 = Khi[s * 36 + f0w + 4];
                uint32_t ah3 = Khi[(s + 8) * 36 + f0w + 4];
                uint32_t al0 = Klo[s * 36 + f0w];
                uint32_t al1 = Klo[(s + 8) * 36 + f0w];
                uint32_t al2 = Klo[s * 36 + f0w + 4];
                uint32_t al3 = Klo[(s + 8) * 36 + f0w + 4];
                #pragma unroll
                for (int nt = 0; nt < 2; nt++) {
                    mma16(xw[mt][nt], ah0, ah1, ah2, ah3, bh[nt][0], bh[nt][1]);
                    mma16(xw[mt][nt], al0, al1, al2, al3, bh[nt][0], bh[nt][1]);
                    mma16(xw[mt][nt], ah0, ah1, ah2, ah3, bl[nt][0], bl[nt][1]);
                }
            }
        }

        // ---- phi epilogue: PhT[m][s] = tf32(exp(+-xw - ss) + eps) ----
        #pragma unroll
        for (int mt = 0; mt < 4; mt++) {
            int s0 = mt * 16 + gid;
            float ssa = ssh[s0], ssb = ssh[s0 + 8];
            #pragma unroll
            for (int nt = 0; nt < 2; nt++) {
                int m0 = w * 16 + nt * 8 + 2 * tq;
                float4 v = xw[mt][nt];
                PhT[m0 * 68 + s0]             = ftf32(__expf( v.x - ssa) + EPSf);
                PhT[(m0 + 1) * 68 + s0]       = ftf32(__expf( v.y - ssa) + EPSf);
                PhT[m0 * 68 + s0 + 8]         = ftf32(__expf( v.z - ssb) + EPSf);
                PhT[(m0 + 1) * 68 + s0 + 8]   = ftf32(__expf( v.w - ssb) + EPSf);
                PhT[(m0 + 128) * 68 + s0]     = ftf32(__expf(-v.x - ssa) + EPSf);
                PhT[(m0 + 129) * 68 + s0]     = ftf32(__expf(-v.y - ssa) + EPSf);
                PhT[(m0 + 128) * 68 + s0 + 8] = ftf32(__expf(-v.z - ssb) + EPSf);
                PhT[(m0 + 129) * 68 + s0 + 8] = ftf32(__expf(-v.w - ssb) + EPSf);
            }
        }
        __syncthreads();

        // ---- acc += PhT . V1   (tf32 k8; warp w owns kv rows [32w, 32w+32)) ----
        #pragma unroll 2
        for (int ks = 0; ks < 8; ks++) {
            float a[2][4];
            #pragma unroll
            for (int mt = 0; mt < 2; mt++) {
                int mr = 32 * w + mt * 16 + gid;
                int sc = ks * 8 + tq;
                a[mt][0] = PhT[mr * 68 + sc];
                a[mt][1] = PhT[(mr + 8) * 68 + sc];
                a[mt][2] = PhT[mr * 68 + sc + 4];
                a[mt][3] = PhT[(mr + 8) * 68 + sc + 4];
            }
            #pragma unroll
            for (int nt = 0; nt < 9; nt++) {
                float b0 = Vs[(ks * 8 + tq) * 72 + nt * 8 + gid];
                float b1 = Vs[(ks * 8 + tq + 4) * 72 + nt * 8 + gid];
                #pragma unroll
                for (int mt = 0; mt < 2; mt++)
                    mma8(acc[mt][nt], a[mt][0], a[mt][1], a[mt][2], a[mt][3], b0, b1);
            }
        }
    }

    // ---- atomic reduce into g_kv ----
    float* gp = g_kv + (size_t)b * 256 * KVPAD;
    #pragma unroll
    for (int mt = 0; mt < 2; mt++) {
        int m0 = 32 * w + mt * 16 + gid;
        #pragma unroll
        for (int nt = 0; nt < 9; nt++) {
            int d0 = nt * 8 + 2 * tq;
            atomicAdd(gp + m0 * KVPAD + d0,           acc[mt][nt].x);
            atomicAdd(gp + m0 * KVPAD + d0 + 1,       acc[mt][nt].y);
            atomicAdd(gp + (m0 + 8) * KVPAD + d0,     acc[mt][nt].z);
            atomicAdd(gp + (m0 + 8) * KVPAD + d0 + 1, acc[mt][nt].w);
        }
    }
}

// ---------------------------------------------------------------------------
// Kernel B: fused  Q -> phi_q -> out = (phi_q . kv) / normalizer
// GEMM1 split-bf16 k16; GEMM4 tf32 k8.
// ---------------------------------------------------------------------------
__global__ __launch_bounds__(256, 1)
void out_kernel(const float* __restrict__ query,
                const float* __restrict__ omega,
                float* __restrict__ outp) {
    const int b   = blockIdx.y;
    const int t0  = blockIdx.x * 128;
    const int tid = threadIdx.x;
    const int w   = tid >> 5;
    const int ln  = tid & 31;
    const int gid = ln >> 2;
    const int tq  = ln & 3;

    float*    PhiQ = sm + B_PHIQ;
    uint32_t* Qhi  = (uint32_t*)(sm + B_QHI);
    uint32_t* Qlo  = (uint32_t*)(sm + B_QLO);
    uint32_t* Ohp  = (uint32_t*)(sm + B_OHIP);
    uint32_t* Olp  = (uint32_t*)(sm + B_OLOP);
    float*    kvs  = sm + B_KVS;
    float*    ssh  = sm + B_SSH;
    float*    prt  = sm + B_PRT;

    // ---- phase-1 loads: Q (bf16 hi/lo split), omega split, kv (tf32) ----
    {
        int r = tid >> 1, h = tid & 1;
        const float4* qg = (const float4*)(query + ((size_t)(b * Tt + t0 + r)) * Ff);
        float ps = 0.f;
        #pragma unroll
        for (int jj = 0; jj < 8; jj++) {
            int fj = h * 8 + jj;
            float4 x = qg[fj];
            ps += x.x * x.x + x.y * x.y + x.z * x.z + x.w * x.w;
            uint32_t hw, lw;
            split2(x.x, x.y, hw, lw);
            Qhi[r * 36 + 2 * fj]     = hw;
            Qlo[r * 36 + 2 * fj]     = lw;
            split2(x.z, x.w, hw, lw);
            Qhi[r * 36 + 2 * fj + 1] = hw;
            Qlo[r * 36 + 2 * fj + 1] = lw;
        }
        prt[tid] = ps;
    }
    for (int i = tid; i < 128 * 32; i += 256) {
        int m = i >> 5, wj = i & 31;
        uint32_t hw, lw;
        split2(omega[m * 64 + 2 * wj], omega[m * 64 + 2 * wj + 1], hw, lw);
        Ohp[m * 36 + wj] = hw;
        Olp[m * 36 + wj] = lw;
    }
    {
        const float4* gk = (const float4*)(g_kv + (size_t)b * 256 * KVPAD);
        for (int i = tid; i < 256 * KVPAD / 4; i += 256) {
            float4 x = gk[i];
            float4 y;
            y.x = ftf32(x.x); y.y = ftf32(x.y); y.z = ftf32(x.z); y.w = ftf32(x.w);
            ((float4*)kvs)[i] = y;
        }
    }
    __syncthreads();
    if (tid < 128) ssh[tid] = 0.5f * (prt[2 * tid] + prt[2 * tid + 1]);
    __syncthreads();

    // ---- XW = Q . Omega^T  (split-bf16 k16; warp w: features [16w,16w+16)) ----
    float4 xw[8][2];
    #pragma unroll
    for (int mt = 0; mt < 8; mt++)
        #pragma unroll
        for (int nt = 0; nt < 2; nt++)
            xw[mt][nt] = make_float4(0.f, 0.f, 0.f, 0.f);

    #pragma unroll
    for (int ks = 0; ks < 4; ks++) {
        int f0w = ks * 8 + tq;
        uint32_t bh[2][2], bl[2][2];
        #pragma unroll
        for (int nt = 0; nt < 2; nt++) {
            int m = w * 16 + nt * 8 + gid;
            bh[nt][0] = Ohp[m * 36 + f0w];  bh[nt][1] = Ohp[m * 36 + f0w + 4];
            bl[nt][0] = Olp[m * 36 + f0w];  bl[nt][1] = Olp[m * 36 + f0w + 4];
        }
        #pragma unroll
        for (int mt = 0; mt < 8; mt++) {
            int t = mt * 16 + gid;
            uint32_t ah0 = Qhi[t * 36 + f0w];
            uint32_t ah1 = Qhi[(t + 8) * 36 + f0w];
            uint32_t ah2 = Qhi[t * 36 + f0w + 4];
            uint32_t ah3 = Qhi[(t + 8) * 36 + f0w + 4];
            uint32_t al0 = Qlo[t * 36 + f0w];
            uint32_t al1 = Qlo[(t + 8) * 36 + f0w];
            uint32_t al2 = Qlo[t * 36 + f0w + 4];
            uint32_t al3 = Qlo[(t + 8) * 36 + f0w + 4];
            #pragma unroll
            for (int nt = 0; nt < 2; nt++) {
                mma16(xw[mt][nt], ah0, ah1, ah2, ah3, bh[nt][0], bh[nt][1]);
                mma16(xw[mt][nt], al0, al1, al2, al3, bh[nt][0], bh[nt][1]);
                mma16(xw[mt][nt], ah0, ah1, ah2, ah3, bl[nt][0], bl[nt][1]);
            }
        }
    }
    __syncthreads();   // all Q/omega packed reads done; PhiQ may overwrite

    // ---- phi epilogue: PhiQ[t][m] = tf32(exp(+-xw - ss) + eps) ----
    #pragma unroll
    for (int mt = 0; mt < 8; mt++) {
        int t = mt * 16 + gid;
        float ssa = ssh[t], ssb = ssh[t + 8];
        #pragma unroll
        for (int nt = 0; nt < 2; nt++) {
            int m0 = w * 16 + nt * 8 + 2 * tq;
            float4 v = xw[mt][nt];
            PhiQ[t * 260 + m0]             = ftf32(__expf( v.x - ssa) + EPSf);
            PhiQ[t * 260 + m0 + 1]         = ftf32(__expf( v.y - ssa) + EPSf);
            PhiQ[(t + 8) * 260 + m0]       = ftf32(__expf( v.z - ssb) + EPSf);
            PhiQ[(t + 8) * 260 + m0 + 1]   = ftf32(__expf( v.w - ssb) + EPSf);
            PhiQ[t * 260 + m0 + 128]       = ftf32(__expf(-v.x - ssa) + EPSf);
            PhiQ[t * 260 + m0 + 129]       = ftf32(__expf(-v.y - ssa) + EPSf);
            PhiQ[(t + 8) * 260 + m0 + 128] = ftf32(__expf(-v.z - ssb) + EPSf);
            PhiQ[(t + 8) * 260 + m0 + 129] = ftf32(__expf(-v.w - ssb) + EPSf);
        }
    }
    __syncthreads();

    // ---- out = PhiQ . kv  (tf32 k8; warp w owns t-rows [16w,16w+16)) ----
    float4 oacc[9];
    #pragma unroll
    for (int nt = 0; nt < 9; nt++) oacc[nt] = make_float4(0.f, 0.f, 0.f, 0.f);

    #pragma unroll 4
    for (int ks = 0; ks < 32; ks++) {
        int tr = 16 * w + gid;
        int mc = ks * 8 + tq;
        float a0 = PhiQ[tr * 260 + mc],       a1 = PhiQ[(tr + 8) * 260 + mc];
        float a2 = PhiQ[tr * 260 + mc + 4],   a3 = PhiQ[(tr + 8) * 260 + mc + 4];
        #pragma unroll
        for (int nt = 0; nt < 9; nt++) {
            float b0 = kvs[(ks * 8 + tq) * KVPAD + nt * 8 + gid];
            float b1 = kvs[(ks * 8 + tq + 4) * KVPAD + nt * 8 + gid];
            mma8(oacc[nt], a0, a1, a2, a3, b0, b1);
        }
    }

    // ---- normalize (normalizer col 64 lives in n-tile 8, lanes tq==0) ----
    float n0 = __shfl_sync(0xffffffffu, oacc[8].x, ln & ~3);
    float n1 = __shfl_sync(0xffffffffu, oacc[8].z, ln & ~3);
    float inv0 = 1.0f / n0;
    float inv1 = 1.0f / n1;

    size_t orow = ((size_t)b * Tt + t0 + 16 * w + gid) * 64;
    #pragma unroll
    for (int nt = 0; nt < 8; nt++) {
        int col = nt * 8 + 2 * tq;
        float2 r0 = make_float2(oacc[nt].x * inv0, oacc[nt].y * inv0);
        float2 r1 = make_float2(oacc[nt].z * inv1, oacc[nt].w * inv1);
        *(float2*)(outp + orow + col)          = r0;
        *(float2*)(outp + orow + 8 * 64 + col) = r1;
    }
}

// ---------------------------------------------------------------------------
// launch
// ---------------------------------------------------------------------------
extern "C" void kernel_launch(void* const* d_in, const int* in_sizes, int n_in,
                              void* d_out, int out_size) {
    const float* query = (const float*)d_in[0];
    const float* value = (const float*)d_in[1];
    const float* key   = (const float*)d_in[2];
    const float* omega = (const float*)d_in[3];
    float* out = (float*)d_out;

    cudaFuncSetAttribute(kv_kernel,  cudaFuncAttributeMaxDynamicSharedMemorySize,
                         A_TOT * (int)sizeof(float));
    cudaFuncSetAttribute(out_kernel, cudaFuncAttributeMaxDynamicSharedMemorySize,
                         B_TOT * (int)sizeof(float));

    zero_kv_kernel<<<(Bb * 256 * KVPAD + 255) / 256, 256>>>();
    kv_kernel<<<dim3(ASPLITS, Bb), 256, A_TOT * sizeof(float)>>>(key, value, omega);
    out_kernel<<<dim3(Tt / 128, Bb), 256, B_TOT * sizeof(float)>>>(query, omega, out);
}

// round 12
// speedup vs baseline: 1.3023x; 1.0159x over previous
#include <cuda_runtime.h>
#include <cuda_bf16.h>
#include <math.h>
#include <stdint.h>

#define Bb 8
#define Tt 8192
#define Ss 8192
#define Ff 64
#define Dd 64
#define EPSf 1e-9f
#define KVPAD 72
#define ASPLITS 16
#define AROWS (Ss/ASPLITS)   /* 512 rows per block in kv kernel */

// kv scratch [b][256][72]; col 64 = normalizer, 65..71 stay zero
__device__ __align__(16) float g_kv[Bb * 256 * KVPAD];

// ---------------------------------------------------------------------------
// helpers
// ---------------------------------------------------------------------------
__device__ __forceinline__ float ftf32(float x) {
    unsigned u;
    asm("cvt.rna.tf32.f32 %0, %1;" : "=r"(u) : "f"(x));
    return __uint_as_float(u);
}

// pack two floats to bf16x2 (lo = x0, hi = x1), round-to-nearest
__device__ __forceinline__ uint32_t packbf(float x0, float x1) {
    uint32_t u;
    asm("cvt.rn.bf16x2.f32 %0, %1, %2;" : "=r"(u) : "f"(x1), "f"(x0));
    return u;
}

// split pair (x0,x1) into bf16 hi word and bf16 lo (residual) word
__device__ __forceinline__ void split2(float x0, float x1,
                                       uint32_t& hw, uint32_t& lw) {
    float h0 = __bfloat162float(__float2bfloat16(x0));
    float h1 = __bfloat162float(__float2bfloat16(x1));
    hw = packbf(x0, x1);
    lw = packbf(x0 - h0, x1 - h1);
}

// tf32 m16n8k8 (GEMM3/GEMM4)
__device__ __forceinline__ void mma8(float4& d,
                                     float a0, float a1, float a2, float a3,
                                     float b0, float b1) {
    asm("mma.sync.aligned.m16n8k8.row.col.f32.tf32.tf32.f32 "
        "{%0,%1,%2,%3},{%4,%5,%6,%7},{%8,%9},{%0,%1,%2,%3};"
        : "+f"(d.x), "+f"(d.y), "+f"(d.z), "+f"(d.w)
        : "r"(__float_as_uint(a0)), "r"(__float_as_uint(a1)),
          "r"(__float_as_uint(a2)), "r"(__float_as_uint(a3)),
          "r"(__float_as_uint(b0)), "r"(__float_as_uint(b1)));
}

// bf16 m16n8k16 (GEMM1)
__device__ __forceinline__ void mma16(float4& d,
                                      uint32_t a0, uint32_t a1,
                                      uint32_t a2, uint32_t a3,
                                      uint32_t b0, uint32_t b1) {
    asm("mma.sync.aligned.m16n8k16.row.col.f32.bf16.bf16.f32 "
        "{%0,%1,%2,%3},{%4,%5,%6,%7},{%8,%9},{%0,%1,%2,%3};"
        : "+f"(d.x), "+f"(d.y), "+f"(d.z), "+f"(d.w)
        : "r"(a0), "r"(a1), "r"(a2), "r"(a3), "r"(b0), "r"(b1));
}

__global__ void zero_kv_kernel() {
    int i = blockIdx.x * blockDim.x + threadIdx.x;
    if (i < Bb * 256 * KVPAD) g_kv[i] = 0.0f;
}

// ---------------------------------------------------------------------------
// smem layouts (32-bit word offsets). Packed bf16x2 arrays use stride 36
// words per 64-element row (conflict-free mma fragment reads).
// ---------------------------------------------------------------------------
// kernel A
#define A_KHI   0        /* [64][36]  packed bf16x2 hi */
#define A_KLO   2304     /* [64][36]  packed bf16x2 lo */
#define A_VS    4608     /* [64][72]  tf32 floats      */
#define A_PHT   9216     /* [256][68] tf32 floats      */
#define A_OHIP  26624    /* [128][36] packed hi        */
#define A_OLOP  31232    /* [128][36] packed lo        */
#define A_SSH   35840    /* [64]  */
#define A_PRT   35904    /* [256] */
#define A_TOT   36160
// kernel B
#define B_PHIQ  0        /* [128][260] floats, aliases packed arrays below */
#define B_QHI   0        /* [128][36] */
#define B_QLO   4608     /* [128][36] */
#define B_OHIP  9216     /* [128][36] */
#define B_OLOP  13824    /* [128][36] */
#define B_KVS   33280    /* [256][72] */
#define B_SSH   51712    /* [128] */
#define B_PRT   51840    /* [256] */
#define B_TOT   52096

extern __shared__ float sm[];

// ---------------------------------------------------------------------------
// Kernel A: fused  K -> phi_k -> kv partial (split-K over S, atomics)
// Per 64-row chunk (register-pipelined K/V prefetch):
//   XW[64x128] = K . Omega^T        (split-bf16, 3-pass m16n8k16)
//   PhT[256][64] = exp(+-XW - ss)   (tf32, transposed)
//   acc[256x64] += PhT . V          (tf32 m16n8k8); normalizer in registers
// ---------------------------------------------------------------------------
__global__ __launch_bounds__(256, 1)
void kv_kernel(const float* __restrict__ key,
               const float* __restrict__ value,
               const float* __restrict__ omega) {
    const int b   = blockIdx.y;
    const int tid = threadIdx.x;
    const int w   = tid >> 5;
    const int ln  = tid & 31;
    const int gid = ln >> 2;
    const int tq  = ln & 3;

    uint32_t* Khi = (uint32_t*)(sm + A_KHI);
    uint32_t* Klo = (uint32_t*)(sm + A_KLO);
    float*    Vs  = sm + A_VS;
    float*    PhT = sm + A_PHT;
    uint32_t* Ohp = (uint32_t*)(sm + A_OHIP);
    uint32_t* Olp = (uint32_t*)(sm + A_OLOP);
    float*    ssh = sm + A_SSH;
    float*    prt = sm + A_PRT;

    // omega -> packed bf16 hi/lo split in smem (once)
    for (int i = tid; i < 128 * 32; i += 256) {
        int m = i >> 5, wj = i & 31;
        uint32_t hw, lw;
        split2(omega[m * 64 + 2 * wj], omega[m * 64 + 2 * wj + 1], hw, lw);
        Ohp[m * 36 + wj] = hw;
        Olp[m * 36 + wj] = lw;
    }

    float4 acc[2][8];
    #pragma unroll
    for (int mt = 0; mt < 2; mt++)
        #pragma unroll
        for (int nt = 0; nt < 8; nt++)
            acc[mt][nt] = make_float4(0.f, 0.f, 0.f, 0.f);
    float nrm[2][2] = {{0.f, 0.f}, {0.f, 0.f}};

    const int row0base = blockIdx.x * AROWS;
    const int r  = tid >> 2;
    const int qd = tid & 3;

    // preload chunk 0 K/V into registers
    float4 kreg[4], vreg[4];
    {
        const float4* kg = (const float4*)(key + ((size_t)(b * Ss + row0base + r)) * Ff);
        const float4* vg = (const float4*)(value + ((size_t)(b * Ss + row0base + r)) * Dd);
        #pragma unroll
        for (int j = 0; j < 4; j++) { kreg[j] = kg[qd * 4 + j]; vreg[j] = vg[qd * 4 + j]; }
    }

    const int NCH = AROWS / 64;
    for (int c = 0; c < NCH; c++) {
        __syncthreads();   // previous-iter PhT/tile reads done before overwrite

        // ---- store staged K (split bf16, +ssq) and V (tf32) to smem ----
        {
            float ps = 0.f;
            #pragma unroll
            for (int j = 0; j < 4; j++) {
                int fj = qd * 4 + j;
                float4 x = kreg[j];
                ps += x.x * x.x + x.y * x.y + x.z * x.z + x.w * x.w;
                uint32_t hw, lw;
                split2(x.x, x.y, hw, lw);
                Khi[r * 36 + 2 * fj] = hw;  Klo[r * 36 + 2 * fj] = lw;
                split2(x.z, x.w, hw, lw);
                Khi[r * 36 + 2 * fj + 1] = hw;  Klo[r * 36 + 2 * fj + 1] = lw;
            }
            prt[tid] = ps;
            #pragma unroll
            for (int j = 0; j < 4; j++) {
                float4 x = vreg[j];
                float4 y;
                y.x = ftf32(x.x); y.y = ftf32(x.y); y.z = ftf32(x.z); y.w = ftf32(x.w);
                ((float4*)(Vs + r * 72))[qd * 4 + j] = y;
            }
            // prefetch next chunk (latency overlaps the whole chunk compute)
            if (c + 1 < NCH) {
                size_t nr = (size_t)(b * Ss + row0base + (c + 1) * 64 + r);
                const float4* kg = (const float4*)(key + nr * Ff);
                const float4* vg = (const float4*)(value + nr * Dd);
                #pragma unroll
                for (int j = 0; j < 4; j++) { kreg[j] = kg[qd * 4 + j]; vreg[j] = vg[qd * 4 + j]; }
            }
        }
        __syncthreads();
        if (tid < 64)
            ssh[tid] = 0.5f * (prt[tid * 4] + prt[tid * 4 + 1] +
                               prt[tid * 4 + 2] + prt[tid * 4 + 3]);
        __syncthreads();

        // ---- XW = K . Omega^T  (split-bf16 k16; warp w: features [16w,16w+16)) ----
        float4 xw[4][2];
        #pragma unroll
        for (int mt = 0; mt < 4; mt++)
            #pragma unroll
            for (int nt = 0; nt < 2; nt++)
                xw[mt][nt] = make_float4(0.f, 0.f, 0.f, 0.f);

        #pragma unroll
        for (int ks = 0; ks < 4; ks++) {
            int f0w = ks * 8 + tq;
            uint32_t bh[2][2], bl[2][2];
            #pragma unroll
            for (int nt = 0; nt < 2; nt++) {
                int m = w * 16 + nt * 8 + gid;
                bh[nt][0] = Ohp[m * 36 + f0w];  bh[nt][1] = Ohp[m * 36 + f0w + 4];
                bl[nt][0] = Olp[m * 36 + f0w];  bl[nt][1] = Olp[m * 36 + f0w + 4];
            }
            #pragma unroll
            for (int mt = 0; mt < 4; mt++) {
                int s = mt * 16 + gid;
                uint32_t ah0 = Khi[s * 36 + f0w],       ah1 = Khi[(s + 8) * 36 + f0w];
                uint32_t ah2 = Khi[s * 36 + f0w + 4],   ah3 = Khi[(s + 8) * 36 + f0w + 4];
                uint32_t al0 = Klo[s * 36 + f0w],       al1 = Klo[(s + 8) * 36 + f0w];
                uint32_t al2 = Klo[s * 36 + f0w + 4],   al3 = Klo[(s + 8) * 36 + f0w + 4];
                #pragma unroll
                for (int nt = 0; nt < 2; nt++) {
                    mma16(xw[mt][nt], ah0, ah1, ah2, ah3, bh[nt][0], bh[nt][1]);
                    mma16(xw[mt][nt], al0, al1, al2, al3, bh[nt][0], bh[nt][1]);
                    mma16(xw[mt][nt], ah0, ah1, ah2, ah3, bl[nt][0], bl[nt][1]);
                }
            }
        }

        // ---- phi epilogue: PhT[m][s] = tf32(exp(+-xw - ss) + eps) ----
        #pragma unroll
        for (int mt = 0; mt < 4; mt++) {
            int s0 = mt * 16 + gid;
            float ssa = ssh[s0], ssb = ssh[s0 + 8];
            #pragma unroll
            for (int nt = 0; nt < 2; nt++) {
                int m0 = w * 16 + nt * 8 + 2 * tq;
                float4 v = xw[mt][nt];
                PhT[m0 * 68 + s0]             = ftf32(__expf( v.x - ssa) + EPSf);
                PhT[(m0 + 1) * 68 + s0]       = ftf32(__expf( v.y - ssa) + EPSf);
                PhT[m0 * 68 + s0 + 8]         = ftf32(__expf( v.z - ssb) + EPSf);
                PhT[(m0 + 1) * 68 + s0 + 8]   = ftf32(__expf( v.w - ssb) + EPSf);
                PhT[(m0 + 128) * 68 + s0]     = ftf32(__expf(-v.x - ssa) + EPSf);
                PhT[(m0 + 129) * 68 + s0]     = ftf32(__expf(-v.y - ssa) + EPSf);
                PhT[(m0 + 128) * 68 + s0 + 8] = ftf32(__expf(-v.z - ssb) + EPSf);
                PhT[(m0 + 129) * 68 + s0 + 8] = ftf32(__expf(-v.w - ssb) + EPSf);
            }
        }
        __syncthreads();

        // ---- acc += PhT . V  (tf32 k8; warp w owns kv rows [32w, 32w+32)) ----
        #pragma unroll 2
        for (int ks = 0; ks < 8; ks++) {
            float a[2][4];
            #pragma unroll
            for (int mt = 0; mt < 2; mt++) {
                int mr = 32 * w + mt * 16 + gid;
                int sc = ks * 8 + tq;
                a[mt][0] = PhT[mr * 68 + sc];
                a[mt][1] = PhT[(mr + 8) * 68 + sc];
                a[mt][2] = PhT[mr * 68 + sc + 4];
                a[mt][3] = PhT[(mr + 8) * 68 + sc + 4];
                // normalizer: every phi of this thread's rows appears exactly once
                nrm[mt][0] += a[mt][0] + a[mt][2];
                nrm[mt][1] += a[mt][1] + a[mt][3];
            }
            #pragma unroll
            for (int nt = 0; nt < 8; nt++) {
                float b0 = Vs[(ks * 8 + tq) * 72 + nt * 8 + gid];
                float b1 = Vs[(ks * 8 + tq + 4) * 72 + nt * 8 + gid];
                #pragma unroll
                for (int mt = 0; mt < 2; mt++)
                    mma8(acc[mt][nt], a[mt][0], a[mt][1], a[mt][2], a[mt][3], b0, b1);
            }
        }
    }

    // ---- atomic reduce into g_kv ----
    float* gp = g_kv + (size_t)b * 256 * KVPAD;
    #pragma unroll
    for (int mt = 0; mt < 2; mt++) {
        int m0 = 32 * w + mt * 16 + gid;
        #pragma unroll
        for (int nt = 0; nt < 8; nt++) {
            int d0 = nt * 8 + 2 * tq;
            atomicAdd(gp + m0 * KVPAD + d0,           acc[mt][nt].x);
            atomicAdd(gp + m0 * KVPAD + d0 + 1,       acc[mt][nt].y);
            atomicAdd(gp + (m0 + 8) * KVPAD + d0,     acc[mt][nt].z);
            atomicAdd(gp + (m0 + 8) * KVPAD + d0 + 1, acc[mt][nt].w);
        }
        float n0 = nrm[mt][0], n1 = nrm[mt][1];
        n0 += __shfl_xor_sync(0xffffffffu, n0, 1);
        n0 += __shfl_xor_sync(0xffffffffu, n0, 2);
        n1 += __shfl_xor_sync(0xffffffffu, n1, 1);
        n1 += __shfl_xor_sync(0xffffffffu, n1, 2);
        if (tq == 0) {
            atomicAdd(gp + m0 * KVPAD + 64,       n0);
            atomicAdd(gp + (m0 + 8) * KVPAD + 64, n1);
        }
    }
}

// ---------------------------------------------------------------------------
// Kernel B: fused  Q -> phi_q -> out = (phi_q . kv) / normalizer
// GEMM1 split-bf16 k16; GEMM4 tf32 k8 (8 n-tiles); normalizer on fma pipe.
// ---------------------------------------------------------------------------
__global__ __launch_bounds__(256, 1)
void out_kernel(const float* __restrict__ query,
                const float* __restrict__ omega,
                float* __restrict__ outp) {
    const int b   = blockIdx.y;
    const int t0  = blockIdx.x * 128;
    const int tid = threadIdx.x;
    const int w   = tid >> 5;
    const int ln  = tid & 31;
    const int gid = ln >> 2;
    const int tq  = ln & 3;

    float*    PhiQ = sm + B_PHIQ;
    uint32_t* Qhi  = (uint32_t*)(sm + B_QHI);
    uint32_t* Qlo  = (uint32_t*)(sm + B_QLO);
    uint32_t* Ohp  = (uint32_t*)(sm + B_OHIP);
    uint32_t* Olp  = (uint32_t*)(sm + B_OLOP);
    float*    kvs  = sm + B_KVS;
    float*    ssh  = sm + B_SSH;
    float*    prt  = sm + B_PRT;

    // ---- phase-1 loads: Q (bf16 hi/lo split), omega split, kv (tf32) ----
    {
        int r = tid >> 1, h = tid & 1;
        const float4* qg = (const float4*)(query + ((size_t)(b * Tt + t0 + r)) * Ff);
        float ps = 0.f;
        #pragma unroll
        for (int jj = 0; jj < 8; jj++) {
            int fj = h * 8 + jj;
            float4 x = qg[fj];
            ps += x.x * x.x + x.y * x.y + x.z * x.z + x.w * x.w;
            uint32_t hw, lw;
            split2(x.x, x.y, hw, lw);
            Qhi[r * 36 + 2 * fj] = hw;  Qlo[r * 36 + 2 * fj] = lw;
            split2(x.z, x.w, hw, lw);
            Qhi[r * 36 + 2 * fj + 1] = hw;  Qlo[r * 36 + 2 * fj + 1] = lw;
        }
        prt[tid] = ps;
    }
    for (int i = tid; i < 128 * 32; i += 256) {
        int m = i >> 5, wj = i & 31;
        uint32_t hw, lw;
        split2(omega[m * 64 + 2 * wj], omega[m * 64 + 2 * wj + 1], hw, lw);
        Ohp[m * 36 + wj] = hw;
        Olp[m * 36 + wj] = lw;
    }
    {
        const float4* gk = (const float4*)(g_kv + (size_t)b * 256 * KVPAD);
        for (int i = tid; i < 256 * KVPAD / 4; i += 256) {
            float4 x = gk[i];
            float4 y;
            y.x = ftf32(x.x); y.y = ftf32(x.y); y.z = ftf32(x.z); y.w = ftf32(x.w);
            ((float4*)kvs)[i] = y;
        }
    }
    __syncthreads();
    if (tid < 128) ssh[tid] = 0.5f * (prt[2 * tid] + prt[2 * tid + 1]);
    __syncthreads();

    // ---- XW = Q . Omega^T  (split-bf16 k16; warp w: features [16w,16w+16)) ----
    float4 xw[8][2];
    #pragma unroll
    for (int mt = 0; mt < 8; mt++)
        #pragma unroll
        for (int nt = 0; nt < 2; nt++)
            xw[mt][nt] = make_float4(0.f, 0.f, 0.f, 0.f);

    #pragma unroll
    for (int ks = 0; ks < 4; ks++) {
        int f0w = ks * 8 + tq;
        uint32_t bh[2][2], bl[2][2];
        #pragma unroll
        for (int nt = 0; nt < 2; nt++) {
            int m = w * 16 + nt * 8 + gid;
            bh[nt][0] = Ohp[m * 36 + f0w];  bh[nt][1] = Ohp[m * 36 + f0w + 4];
            bl[nt][0] = Olp[m * 36 + f0w];  bl[nt][1] = Olp[m * 36 + f0w + 4];
        }
        #pragma unroll
        for (int mt = 0; mt < 8; mt++) {
            int t = mt * 16 + gid;
            uint32_t ah0 = Qhi[t * 36 + f0w],       ah1 = Qhi[(t + 8) * 36 + f0w];
            uint32_t ah2 = Qhi[t * 36 + f0w + 4],   ah3 = Qhi[(t + 8) * 36 + f0w + 4];
            uint32_t al0 = Qlo[t * 36 + f0w],       al1 = Qlo[(t + 8) * 36 + f0w];
            uint32_t al2 = Qlo[t * 36 + f0w + 4],   al3 = Qlo[(t + 8) * 36 + f0w + 4];
            #pragma unroll
            for (int nt = 0; nt < 2; nt++) {
                mma16(xw[mt][nt], ah0, ah1, ah2, ah3, bh[nt][0], bh[nt][1]);
                mma16(xw[mt][nt], al0, al1, al2, al3, bh[nt][0], bh[nt][1]);
                mma16(xw[mt][nt], ah0, ah1, ah2, ah3, bl[nt][0], bl[nt][1]);
            }
        }
    }
    __syncthreads();   // Q/omega packed reads done; PhiQ may overwrite

    // ---- phi epilogue: PhiQ[t][m] = tf32(exp(+-xw - ss) + eps) ----
    #pragma unroll
    for (int mt = 0; mt < 8; mt++) {
        int t = mt * 16 + gid;
        float ssa = ssh[t], ssb = ssh[t + 8];
        #pragma unroll
        for (int nt = 0; nt < 2; nt++) {
            int m0 = w * 16 + nt * 8 + 2 * tq;
            float4 v = xw[mt][nt];
            PhiQ[t * 260 + m0]             = ftf32(__expf( v.x - ssa) + EPSf);
            PhiQ[t * 260 + m0 + 1]         = ftf32(__expf( v.y - ssa) + EPSf);
            PhiQ[(t + 8) * 260 + m0]       = ftf32(__expf( v.z - ssb) + EPSf);
            PhiQ[(t + 8) * 260 + m0 + 1]   = ftf32(__expf( v.w - ssb) + EPSf);
            PhiQ[t * 260 + m0 + 128]       = ftf32(__expf(-v.x - ssa) + EPSf);
            PhiQ[t * 260 + m0 + 129]       = ftf32(__expf(-v.y - ssa) + EPSf);
            PhiQ[(t + 8) * 260 + m0 + 128] = ftf32(__expf(-v.z - ssb) + EPSf);
            PhiQ[(t + 8) * 260 + m0 + 129] = ftf32(__expf(-v.w - ssb) + EPSf);
        }
    }
    __syncthreads();

    // ---- out = PhiQ . kv  (tf32 k8, 8 n-tiles; normalizer on fma pipe) ----
    float4 oacc[8];
    #pragma unroll
    for (int nt = 0; nt < 8; nt++) oacc[nt] = make_float4(0.f, 0.f, 0.f, 0.f);
    float nrm0 = 0.f, nrm1 = 0.f;

    const int tr = 16 * w + gid;
    #pragma unroll 4
    for (int ks = 0; ks < 32; ks++) {
        int mc = ks * 8 + tq;
        float a0 = PhiQ[tr * 260 + mc],       a1 = PhiQ[(tr + 8) * 260 + mc];
        float a2 = PhiQ[tr * 260 + mc + 4],   a3 = PhiQ[(tr + 8) * 260 + mc + 4];
        float kn0 = kvs[mc * KVPAD + 64];
        float kn1 = kvs[(mc + 4) * KVPAD + 64];
        nrm0 += a0 * kn0 + a2 * kn1;
        nrm1 += a1 * kn0 + a3 * kn1;
        #pragma unroll
        for (int nt = 0; nt < 8; nt++) {
            float b0 = kvs[mc * KVPAD + nt * 8 + gid];
            float b1 = kvs[(mc + 4) * KVPAD + nt * 8 + gid];
            mma8(oacc[nt], a0, a1, a2, a3, b0, b1);
        }
    }

    // quad-reduce the normalizer partials (lanes differ only in tq)
    nrm0 += __shfl_xor_sync(0xffffffffu, nrm0, 1);
    nrm0 += __shfl_xor_sync(0xffffffffu, nrm0, 2);
    nrm1 += __shfl_xor_sync(0xffffffffu, nrm1, 1);
    nrm1 += __shfl_xor_sync(0xffffffffu, nrm1, 2);
    float inv0 = 1.0f / nrm0;
    float inv1 = 1.0f / nrm1;

    size_t orow = ((size_t)b * Tt + t0 + tr) * 64;
    #pragma unroll
    for (int nt = 0; nt < 8; nt++) {
        int col = nt * 8 + 2 * tq;
        float2 r0 = make_float2(oacc[nt].x * inv0, oacc[nt].y * inv0);
        float2 r1 = make_float2(oacc[nt].z * inv1, oacc[nt].w * inv1);
        *(float2*)(outp + orow + col)          = r0;
        *(float2*)(outp + orow + 8 * 64 + col) = r1;
    }
}

// ---------------------------------------------------------------------------
// launch
// ---------------------------------------------------------------------------
extern "C" void kernel_launch(void* const* d_in, const int* in_sizes, int n_in,
                              void* d_out, int out_size) {
    const float* query = (const float*)d_in[0];
    const float* value = (const float*)d_in[1];
    const float* key   = (const float*)d_in[2];
    const float* omega = (const float*)d_in[3];
    float* out = (float*)d_out;

    cudaFuncSetAttribute(kv_kernel,  cudaFuncAttributeMaxDynamicSharedMemorySize,
                         A_TOT * (int)sizeof(float));
    cudaFuncSetAttribute(out_kernel, cudaFuncAttributeMaxDynamicSharedMemorySize,
                         B_TOT * (int)sizeof(float));

    zero_kv_kernel<<<(Bb * 256 * KVPAD + 255) / 256, 256>>>();
    kv_kernel<<<dim3(ASPLITS, Bb), 256, A_TOT * sizeof(float)>>>(key, value, omega);
    out_kernel<<<dim3(Tt / 128, Bb), 256, B_TOT * sizeof(float)>>>(query, omega, out);
}